// round 3
// baseline (speedup 1.0000x reference)
#include <cuda_runtime.h>
#include <math.h>

#define Jn 21
#define NHn 7
#define Hn 4
#define HDn 64
#define ALPHAc 0.2f
#define NTHREADS 256

// ---- shared memory layout (float offsets) ----
#define HPT_LD 28                                   // hpT row stride (pad for banks + 16B align)
constexpr int OFF_WOUT = 0;                         // 256*64 = 16384
constexpr int OFF_H    = OFF_WOUT + 256 * 64;       // 4*21*64 = 5376
constexpr int OFF_HPT  = OFF_H + Hn * Jn * HDn;     // 256*28  = 7168
constexpr int OFF_ATTN = OFF_HPT + 256 * HPT_LD;    // 4*21*21 = 1764
constexpr int OFF_WH   = OFF_ATTN + Hn * Jn * Jn;   // 4*7*64  = 1792
constexpr int OFF_X    = OFF_WH + Hn * NHn * HDn;   // 21*8    = 168
constexpr int OFF_A1   = OFF_X + Jn * 8;            // 4*64
constexpr int OFF_A2   = OFF_A1 + Hn * HDn;         // 4*64
constexpr int OFF_AO   = OFF_A2 + Hn * HDn;         // 128
constexpr int OFF_F1   = OFF_AO + 2 * HDn;          // 84
constexpr int OFF_F2   = OFF_F1 + Hn * Jn;          // 84
constexpr int OFF_H2   = OFF_F2 + Hn * Jn;          // 21*64 = 1344
constexpr int OFF_HP2  = OFF_H2 + Jn * HDn;         // 1344
constexpr int OFF_F1B  = OFF_HP2 + Jn * HDn;        // 21
constexpr int OFF_F2B  = OFF_F1B + Jn;              // 21
constexpr int OFF_ATT2 = OFF_F2B + Jn;              // 441
constexpr int SMEM_FLOATS = OFF_ATT2 + Jn * Jn;
constexpr int SMEM_BYTES  = SMEM_FLOATS * 4;        // ~146.5 KB

__device__ __forceinline__ float warp_sum(float v) {
    #pragma unroll
    for (int o = 16; o > 0; o >>= 1) v += __shfl_xor_sync(0xffffffffu, v, o);
    return v;
}
__device__ __forceinline__ float warp_max(float v) {
    #pragma unroll
    for (int o = 16; o > 0; o >>= 1) v = fmaxf(v, __shfl_xor_sync(0xffffffffu, v, o));
    return v;
}
__device__ __forceinline__ float elu1(float x) {
    return x > 0.f ? x : expm1f(x);
}

__global__ void __launch_bounds__(NTHREADS, 1)
gat_kernel(const float* __restrict__ inp,
           const float* __restrict__ W_heads,
           const float* __restrict__ a_heads,
           const float* __restrict__ W_out,
           const float* __restrict__ a_out,
           float* __restrict__ out)
{
    extern __shared__ float sm[];
    const int tid  = threadIdx.x;
    const int lane = tid & 31;
    const int wid  = tid >> 5;
    const int pair = blockIdx.x;

    // ---------------- Phase 0: cooperative loads ----------------
    {
        const float4* src = (const float4*)W_out;
        float4* dst = (float4*)(sm + OFF_WOUT);
        #pragma unroll
        for (int i = tid; i < 256 * 64 / 4; i += NTHREADS) dst[i] = src[i];
    }
    for (int i = tid; i < Hn * NHn * HDn; i += NTHREADS) sm[OFF_WH + i] = W_heads[i];
    for (int i = tid; i < Hn * 2 * HDn; i += NTHREADS) {
        int h = i / (2 * HDn), r = i % (2 * HDn);
        if (r < HDn) sm[OFF_A1 + h * HDn + r] = a_heads[i];
        else         sm[OFF_A2 + h * HDn + (r - HDn)] = a_heads[i];
    }
    if (tid < 2 * HDn) sm[OFF_AO + tid] = a_out[tid];
    {
        const float* ip = inp + (long long)pair * (Jn * NHn);
        if (tid < Jn * NHn) {
            float v = ip[tid];
            int j, c;
            if (tid < Jn * 3)          { j = tid / 3;         c = tid % 3; }
            else if (tid < 2 * Jn * 3) { int t = tid - Jn * 3; j = t / 3;  c = 3 + t % 3; }
            else                       { j = tid - 2 * Jn * 3; c = 6; }
            sm[OFF_X + j * 8 + c] = v;
        }
    }
    __syncthreads();

    // ---------------- Phase 1: h[hh][j][d] = sum_n x[j][n] * Wh[hh][n][d] ----------------
    for (int idx = tid; idx < Hn * Jn * HDn; idx += NTHREADS) {
        int d  = idx & 63;
        int hj = idx >> 6;          // hh*21 + j
        int j  = hj % Jn;
        int hh = hj / Jn;
        const float* xr = sm + OFF_X + j * 8;
        const float* wr = sm + OFF_WH + hh * NHn * HDn + d;
        float acc = 0.f;
        #pragma unroll
        for (int n = 0; n < NHn; n++) acc = fmaf(xr[n], wr[n * HDn], acc);
        sm[OFF_H + idx] = acc;
    }
    __syncthreads();

    // ---------------- Phase 1b: f1/f2 per head (warp reductions) ----------------
    if (wid < Hn) {
        const int hh = wid;
        const float a1v0 = sm[OFF_A1 + hh * HDn + lane];
        const float a1v1 = sm[OFF_A1 + hh * HDn + lane + 32];
        const float a2v0 = sm[OFF_A2 + hh * HDn + lane];
        const float a2v1 = sm[OFF_A2 + hh * HDn + lane + 32];
        for (int j = 0; j < Jn; j++) {
            const float* hr = sm + OFF_H + (hh * Jn + j) * HDn;
            float h0 = hr[lane], h1 = hr[lane + 32];
            float s1 = warp_sum(fmaf(h0, a1v0, h1 * a1v1));
            float s2 = warp_sum(fmaf(h0, a2v0, h1 * a2v1));
            if (lane == 0) { sm[OFF_F1 + hh * Jn + j] = s1; sm[OFF_F2 + hh * Jn + j] = s2; }
        }
    }
    __syncthreads();

    // ---------------- Phase 2a: per-row softmax of leaky_relu(f1_i + f2_j) ----------------
    if (tid < Hn * Jn) {
        const int hh = tid / Jn;
        const float fi = sm[OFF_F1 + tid];
        const float* f2r = sm + OFF_F2 + hh * Jn;
        float ebuf[Jn];
        float m = -1e30f;
        #pragma unroll
        for (int j = 0; j < Jn; j++) {
            float e = fi + f2r[j];
            e = e > 0.f ? e : ALPHAc * e;
            ebuf[j] = e;
            m = fmaxf(m, e);
        }
        float s = 0.f;
        #pragma unroll
        for (int j = 0; j < Jn; j++) { float t = __expf(ebuf[j] - m); ebuf[j] = t; s += t; }
        float inv = 1.f / s;
        #pragma unroll
        for (int j = 0; j < Jn; j++) sm[OFF_ATTN + tid * Jn + j] = ebuf[j] * inv;
    }
    __syncthreads();

    // ---------------- Phase 2b: hp = elu(attn @ h), stored transposed hpT[k][j] ----------------
    // unit = (hh, i, dq) : dq indexes a float4 of d
    for (int u = tid; u < Hn * Jn * (HDn / 4); u += NTHREADS) {
        int dq = u & 15;
        int hi = u >> 4;            // hh*21 + i
        int i  = hi % Jn;
        int hh = hi / Jn;
        const float* ar = sm + OFF_ATTN + hi * Jn;
        float4 acc = make_float4(0.f, 0.f, 0.f, 0.f);
        #pragma unroll
        for (int j = 0; j < Jn; j++) {
            float a = ar[j];
            float4 hv = *(const float4*)(sm + OFF_H + (hh * Jn + j) * HDn + dq * 4);
            acc.x = fmaf(a, hv.x, acc.x);
            acc.y = fmaf(a, hv.y, acc.y);
            acc.z = fmaf(a, hv.z, acc.z);
            acc.w = fmaf(a, hv.w, acc.w);
        }
        int k = hh * HDn + dq * 4;  // row in hpT (= h*64 + d')
        float* base = sm + OFF_HPT + k * HPT_LD + i;
        base[0 * HPT_LD] = elu1(acc.x);
        base[1 * HPT_LD] = elu1(acc.y);
        base[2 * HPT_LD] = elu1(acc.z);
        base[3 * HPT_LD] = elu1(acc.w);
    }
    __syncthreads();

    // ---------------- Phase 3: h2[j][d] = sum_k hpT[k][j] * Wout[k][d]  (21x256x64) ----------------
    if (wid < 6) {
        const int jq = wid;         // j in {4jq..4jq+3}
        const int d  = lane;
        float acc[8] = {0.f, 0.f, 0.f, 0.f, 0.f, 0.f, 0.f, 0.f};
        const float* wp = sm + OFF_WOUT + d;
        const float* hp = sm + OFF_HPT + 4 * jq;
        #pragma unroll 4
        for (int k = 0; k < Hn * HDn; k++) {
            float4 hv = *(const float4*)(hp + k * HPT_LD);   // warp-broadcast
            float w0 = wp[k * 64];
            float w1 = wp[k * 64 + 32];
            acc[0] = fmaf(hv.x, w0, acc[0]); acc[1] = fmaf(hv.x, w1, acc[1]);
            acc[2] = fmaf(hv.y, w0, acc[2]); acc[3] = fmaf(hv.y, w1, acc[3]);
            acc[4] = fmaf(hv.z, w0, acc[4]); acc[5] = fmaf(hv.z, w1, acc[5]);
            acc[6] = fmaf(hv.w, w0, acc[6]); acc[7] = fmaf(hv.w, w1, acc[7]);
        }
        #pragma unroll
        for (int jj = 0; jj < 4; jj++) {
            int j = jq * 4 + jj;
            if (j < Jn) {
                sm[OFF_H2 + j * HDn + d]      = acc[2 * jj];
                sm[OFF_H2 + j * HDn + d + 32] = acc[2 * jj + 1];
            }
        }
    }
    __syncthreads();

    // ---------------- Phase 4a: f1b/f2b over h2 ----------------
    if (wid < 4) {
        const float ao10 = sm[OFF_AO + lane],       ao11 = sm[OFF_AO + lane + 32];
        const float ao20 = sm[OFF_AO + HDn + lane], ao21 = sm[OFF_AO + HDn + lane + 32];
        for (int j = wid; j < Jn; j += 4) {
            const float* hr = sm + OFF_H2 + j * HDn;
            float h0 = hr[lane], h1 = hr[lane + 32];
            float s1 = warp_sum(fmaf(h0, ao10, h1 * ao11));
            float s2 = warp_sum(fmaf(h0, ao20, h1 * ao21));
            if (lane == 0) { sm[OFF_F1B + j] = s1; sm[OFF_F2B + j] = s2; }
        }
    }
    __syncthreads();

    // ---------------- Phase 4b: second softmax ----------------
    if (tid < Jn) {
        const float fi = sm[OFF_F1B + tid];
        float ebuf[Jn];
        float m = -1e30f;
        #pragma unroll
        for (int j = 0; j < Jn; j++) {
            float e = fi + sm[OFF_F2B + j];
            e = e > 0.f ? e : ALPHAc * e;
            ebuf[j] = e;
            m = fmaxf(m, e);
        }
        float s = 0.f;
        #pragma unroll
        for (int j = 0; j < Jn; j++) { float t = __expf(ebuf[j] - m); ebuf[j] = t; s += t; }
        float inv = 1.f / s;
        #pragma unroll
        for (int j = 0; j < Jn; j++) sm[OFF_ATT2 + tid * Jn + j] = ebuf[j] * inv;
    }
    __syncthreads();

    // ---------------- Phase 4c: hp2 = elu(attn2 @ h2) ----------------
    for (int u = tid; u < Jn * (HDn / 4); u += NTHREADS) {
        int dq = u & 15;
        int i  = u >> 4;
        const float* ar = sm + OFF_ATT2 + i * Jn;
        float4 acc = make_float4(0.f, 0.f, 0.f, 0.f);
        #pragma unroll
        for (int j = 0; j < Jn; j++) {
            float a = ar[j];
            float4 hv = *(const float4*)(sm + OFF_H2 + j * HDn + dq * 4);
            acc.x = fmaf(a, hv.x, acc.x);
            acc.y = fmaf(a, hv.y, acc.y);
            acc.z = fmaf(a, hv.z, acc.z);
            acc.w = fmaf(a, hv.w, acc.w);
        }
        float4 r;
        r.x = elu1(acc.x); r.y = elu1(acc.y); r.z = elu1(acc.z); r.w = elu1(acc.w);
        *(float4*)(sm + OFF_HP2 + i * HDn + dq * 4) = r;
    }
    __syncthreads();

    // ---------------- Phase 4d: log_softmax over d, write out ----------------
    for (int i = wid; i < Jn; i += 8) {
        float v0 = sm[OFF_HP2 + i * HDn + lane];
        float v1 = sm[OFF_HP2 + i * HDn + lane + 32];
        float m = warp_max(fmaxf(v0, v1));
        float s = warp_sum(__expf(v0 - m) + __expf(v1 - m));
        float lse = m + __logf(s);
        float* op = out + (long long)pair * (Jn * HDn) + i * HDn;
        op[lane]      = v0 - lse;
        op[lane + 32] = v1 - lse;
    }
}

extern "C" void kernel_launch(void* const* d_in, const int* in_sizes, int n_in,
                              void* d_out, int out_size)
{
    const float* inp = (const float*)d_in[0];
    // d_in[1] = seq_start_end (unused by the reference computation)
    const float* Wh  = (const float*)d_in[2];
    const float* ah  = (const float*)d_in[3];
    const float* Wo  = (const float*)d_in[4];
    const float* ao  = (const float*)d_in[5];
    float* out = (float*)d_out;

    const int npairs = in_sizes[0] / (Jn * NHn);   // 16*1024 = 16384

    cudaFuncSetAttribute(gat_kernel, cudaFuncAttributeMaxDynamicSharedMemorySize, SMEM_BYTES);
    gat_kernel<<<npairs, NTHREADS, SMEM_BYTES>>>(inp, Wh, ah, Wo, ao, out);
}

// round 4
// speedup vs baseline: 1.7109x; 1.7109x over previous
#include <cuda_runtime.h>
#include <math.h>

#define Jn 21
#define NHn 7
#define Hn 4
#define HDn 64
#define NTHREADS 256
#define HPT_LD 22

typedef unsigned long long ull;

// ---- shared memory layout (float offsets) ----
constexpr int OFF_H    = 0;                           // 4*21*64 = 5376
constexpr int OFF_HPT  = OFF_H + Hn * Jn * HDn;       // 256*22  = 5632
constexpr int OFF_ATTN = OFF_HPT + 256 * HPT_LD;      // 4*21*21 = 1764
constexpr int OFF_WH   = OFF_ATTN + Hn * Jn * Jn;     // 4*7*64  = 1792
constexpr int OFF_XD   = OFF_WH + Hn * NHn * HDn;     // 21*8*2  = 336 (dup f2)
constexpr int OFF_A12  = OFF_XD + Jn * 8 * 2;         // 4*64*2  = 512 (a1,a2 interleaved)
constexpr int OFF_AO12 = OFF_A12 + Hn * HDn * 2;      // 128
constexpr int OFF_F1   = OFF_AO12 + 2 * HDn;          // 84
constexpr int OFF_F2   = OFF_F1 + Hn * Jn;            // 84
constexpr int OFF_H2   = OFF_F2 + Hn * Jn;            // 21*64 = 1344 (%4==0)
constexpr int OFF_HP2  = OFF_H2 + Jn * HDn;           // 1344
constexpr int OFF_F1B  = OFF_HP2 + Jn * HDn;          // 21
constexpr int OFF_F2B  = OFF_F1B + Jn;                // 21
constexpr int OFF_AT2D = OFF_F2B + Jn;                // 21*21*2 = 882 (dup f2)
constexpr int SMEM_FLOATS = OFF_AT2D + Jn * Jn * 2;
constexpr int SMEM_BYTES  = SMEM_FLOATS * 4;          // ~75.5 KB -> 2 CTAs/SM

static_assert(OFF_H2 % 4 == 0, "H2 float4 align");
static_assert(OFF_HP2 % 4 == 0, "HP2 float4 align");
static_assert(OFF_HPT % 2 == 0 && OFF_XD % 2 == 0 && OFF_A12 % 2 == 0 &&
              OFF_AO12 % 2 == 0 && OFF_AT2D % 2 == 0, "f2 align");

__device__ __forceinline__ void ffma2(ull& d, ull a, ull b) {
    asm("fma.rn.f32x2 %0, %1, %2, %3;" : "=l"(d) : "l"(a), "l"(b), "l"(d));
}
__device__ __forceinline__ ull dup2(float x) {
    ull r; unsigned xi = __float_as_uint(x);
    asm("mov.b64 %0, {%1, %1};" : "=l"(r) : "r"(xi));
    return r;
}
__device__ __forceinline__ float2 unpk(ull v) {
    float2 r;
    asm("mov.b64 {%0, %1}, %2;" : "=f"(r.x), "=f"(r.y) : "l"(v));
    return r;
}
__device__ __forceinline__ float warp_sum(float v) {
    #pragma unroll
    for (int o = 16; o > 0; o >>= 1) v += __shfl_xor_sync(0xffffffffu, v, o);
    return v;
}
__device__ __forceinline__ float warp_max(float v) {
    #pragma unroll
    for (int o = 16; o > 0; o >>= 1) v = fmaxf(v, __shfl_xor_sync(0xffffffffu, v, o));
    return v;
}
__device__ __forceinline__ float elu1(float x) {
    return x > 0.f ? x : (__expf(x) - 1.f);
}

__global__ void __launch_bounds__(NTHREADS, 2)
gat_kernel(const float* __restrict__ inp,
           const float* __restrict__ W_heads,
           const float* __restrict__ a_heads,
           const float* __restrict__ W_out,
           const float* __restrict__ a_out,
           float* __restrict__ out)
{
    extern __shared__ float sm[];
    const int tid  = threadIdx.x;
    const int lane = tid & 31;
    const int wid  = tid >> 5;
    const int pair = blockIdx.x;

    // ---------------- Phase 0: cooperative loads (no W_out copy) ----------------
    for (int i = tid; i < Hn * NHn * HDn; i += NTHREADS) sm[OFF_WH + i] = W_heads[i];
    if (tid < Hn * HDn) {
        int hh = tid >> 6, kk = tid & 63;
        ((float2*)(sm + OFF_A12))[tid] =
            make_float2(a_heads[hh * 128 + kk], a_heads[hh * 128 + 64 + kk]);
    }
    if (tid < HDn)
        ((float2*)(sm + OFF_AO12))[tid] = make_float2(a_out[tid], a_out[64 + tid]);
    {
        const float* ip = inp + (long long)pair * (Jn * NHn);
        if (tid < Jn * NHn) {
            float v = ip[tid];
            int j, c;
            if (tid < Jn * 3)          { j = tid / 3;          c = tid % 3; }
            else if (tid < 2 * Jn * 3) { int t = tid - Jn * 3; j = t / 3;  c = 3 + t % 3; }
            else                       { j = tid - 2 * Jn * 3; c = 6; }
            ((float2*)(sm + OFF_XD))[j * 8 + c] = make_float2(v, v);
        }
    }
    __syncthreads();

    // ---------------- Phase 1: h = x @ W_heads (packed f32x2, W cached in regs) ----------------
    {
        const int hh = tid >> 6;
        const int rem = tid & 63;
        const int jh = rem >> 5;           // warp-uniform j-half
        const int dp = rem & 31;           // d pair index (d = 2dp)
        const ull* wsm = (const ull*)(sm + OFF_WH);
        ull w[NHn];
        #pragma unroll
        for (int n = 0; n < NHn; n++) w[n] = wsm[hh * 224 + n * 32 + dp];
        const int j0 = jh * 11, cnt = 11 - jh;
        const ull* xd = (const ull*)(sm + OFF_XD);
        ull* hout = (ull*)(sm + OFF_H);
        for (int jj = 0; jj < cnt; jj++) {
            const int j = j0 + jj;
            const ull* xr = xd + j * 8;
            ull acc = 0ull;
            #pragma unroll
            for (int n = 0; n < NHn; n++) ffma2(acc, xr[n], w[n]);
            hout[(hh * Jn + j) * 32 + dp] = acc;
        }
    }
    __syncthreads();

    // ---------------- Phase 1b: f1/f2 dots (XOR lane rotation, packed a1/a2) ----------------
    if (tid < Hn * Jn) {
        const int row = tid;
        const int hh = row / Jn;
        const int c = row & 63;
        const float* hrow = sm + OFF_H + row * 64;
        const ull* arow = (const ull*)(sm + OFF_A12) + hh * 64;
        ull a0 = 0ull, a1 = 0ull;
        #pragma unroll
        for (int t = 0; t < 64; t += 2) {
            int k0 = t ^ c, k1 = (t + 1) ^ c;
            ffma2(a0, dup2(hrow[k0]), arow[k0]);
            ffma2(a1, dup2(hrow[k1]), arow[k1]);
        }
        float2 r0 = unpk(a0), r1 = unpk(a1);
        sm[OFF_F1 + row] = r0.x + r1.x;
        sm[OFF_F2 + row] = r0.y + r1.y;
    }
    __syncthreads();

    // ---------------- Phase 2a: per-row softmax of leaky_relu(f1_i + f2_j) ----------------
    if (tid < Hn * Jn) {
        const int hh = tid / Jn;
        const float fi = sm[OFF_F1 + tid];
        const float* f2r = sm + OFF_F2 + hh * Jn;
        float ebuf[Jn];
        float m = -1e30f;
        #pragma unroll
        for (int j = 0; j < Jn; j++) {
            float e = fi + f2r[j];
            e = e > 0.f ? e : 0.2f * e;
            ebuf[j] = e;
            m = fmaxf(m, e);
        }
        float s = 0.f;
        #pragma unroll
        for (int j = 0; j < Jn; j++) { float t = __expf(ebuf[j] - m); ebuf[j] = t; s += t; }
        float inv = 1.f / s;
        #pragma unroll
        for (int j = 0; j < Jn; j++) sm[OFF_ATTN + tid * Jn + j] = ebuf[j] * inv;
    }
    __syncthreads();

    // ---------------- Phase 2b: hp = elu(attn @ h), stored transposed hpT[k][i] ----------------
    for (int u = tid; u < Hn * Jn * (HDn / 4); u += NTHREADS) {
        const int dq = u & 15;
        const int hi = u >> 4;             // hh*21 + i
        const int hh = hi / Jn;
        const int i  = hi - hh * Jn;
        const float* ar = sm + OFF_ATTN + hi * Jn;
        const char* hbytes = (const char*)(sm + OFF_H + hh * Jn * HDn + dq * 4);
        ull acc01 = 0ull, acc23 = 0ull;
        #pragma unroll
        for (int j = 0; j < Jn; j++) {
            ull a2 = dup2(ar[j]);
            ulonglong2 hv = *(const ulonglong2*)(hbytes + j * (HDn * 4));
            ffma2(acc01, a2, hv.x);
            ffma2(acc23, a2, hv.y);
        }
        float2 e01 = unpk(acc01), e23 = unpk(acc23);
        float* b = sm + OFF_HPT + (hh * HDn + dq * 4) * HPT_LD + i;
        b[0 * HPT_LD] = elu1(e01.x);
        b[1 * HPT_LD] = elu1(e01.y);
        b[2 * HPT_LD] = elu1(e23.x);
        b[3 * HPT_LD] = elu1(e23.y);
    }
    __syncthreads();

    // ---------------- Phase 3: h2 = hp @ W_out (21x256x64), W_out via __ldg ----------------
    if (wid < 6) {
        const int jq = wid;
        const int jh = lane >> 4;          // j sub-pair
        const int dq = lane & 15;          // d = 4*dq
        const float2* hp = (const float2*)(sm + OFF_HPT) + 2 * jq + jh;  // + k*11
        const ulonglong2* wp = (const ulonglong2*)W_out + dq;            // + k*16
        ull acc0 = 0ull, acc1 = 0ull, acc2 = 0ull, acc3 = 0ull;
        #pragma unroll 4
        for (int k = 0; k < Hn * HDn; k++) {
            float2 hv = hp[k * (HPT_LD / 2)];
            ulonglong2 w = __ldg(wp + k * 16);
            ull hx = dup2(hv.x), hy = dup2(hv.y);
            ffma2(acc0, hx, w.x);
            ffma2(acc1, hx, w.y);
            ffma2(acc2, hy, w.x);
            ffma2(acc3, hy, w.y);
        }
        const int jb = 4 * jq + 2 * jh;
        if (jb < Jn) {
            ull* h2 = (ull*)(sm + OFF_H2) + jb * 32 + dq * 2;
            h2[0] = acc0; h2[1] = acc1;
        }
        if (jb + 1 < Jn) {
            ull* h2 = (ull*)(sm + OFF_H2) + (jb + 1) * 32 + dq * 2;
            h2[0] = acc2; h2[1] = acc3;
        }
    }
    __syncthreads();

    // ---------------- Phase 4a: f1b/f2b dots over h2 ----------------
    if (tid < Jn) {
        const int row = tid;
        const int c = row & 63;
        const float* hrow = sm + OFF_H2 + row * 64;
        const ull* arow = (const ull*)(sm + OFF_AO12);
        ull a0 = 0ull, a1 = 0ull;
        #pragma unroll
        for (int t = 0; t < 64; t += 2) {
            int k0 = t ^ c, k1 = (t + 1) ^ c;
            ffma2(a0, dup2(hrow[k0]), arow[k0]);
            ffma2(a1, dup2(hrow[k1]), arow[k1]);
        }
        float2 r0 = unpk(a0), r1 = unpk(a1);
        sm[OFF_F1B + row] = r0.x + r1.x;
        sm[OFF_F2B + row] = r0.y + r1.y;
    }
    __syncthreads();

    // ---------------- Phase 4b: second softmax (duplicated store) ----------------
    if (tid < Jn) {
        const float fi = sm[OFF_F1B + tid];
        float ebuf[Jn];
        float m = -1e30f;
        #pragma unroll
        for (int j = 0; j < Jn; j++) {
            float e = fi + sm[OFF_F2B + j];
            e = e > 0.f ? e : 0.2f * e;
            ebuf[j] = e;
            m = fmaxf(m, e);
        }
        float s = 0.f;
        #pragma unroll
        for (int j = 0; j < Jn; j++) { float t = __expf(ebuf[j] - m); ebuf[j] = t; s += t; }
        float inv = 1.f / s;
        #pragma unroll
        for (int j = 0; j < Jn; j++)
            ((float2*)(sm + OFF_AT2D))[tid * Jn + j] = make_float2(ebuf[j] * inv, ebuf[j] * inv);
    }
    __syncthreads();

    // ---------------- Phase 4c: hp2 = elu(attn2 @ h2) ----------------
    for (int u = tid; u < Jn * (HDn / 4); u += NTHREADS) {
        const int dq = u & 15;
        const int i  = u >> 4;
        const ull* ar = (const ull*)(sm + OFF_AT2D) + i * Jn;
        const char* hbytes = (const char*)(sm + OFF_H2 + dq * 4);
        ull acc01 = 0ull, acc23 = 0ull;
        #pragma unroll
        for (int j = 0; j < Jn; j++) {
            ull a2 = ar[j];
            ulonglong2 hv = *(const ulonglong2*)(hbytes + j * (HDn * 4));
            ffma2(acc01, a2, hv.x);
            ffma2(acc23, a2, hv.y);
        }
        float2 e01 = unpk(acc01), e23 = unpk(acc23);
        float4 r;
        r.x = elu1(e01.x); r.y = elu1(e01.y); r.z = elu1(e23.x); r.w = elu1(e23.y);
        *(float4*)(sm + OFF_HP2 + i * HDn + dq * 4) = r;
    }
    __syncthreads();

    // ---------------- Phase 4d: log_softmax over d, write out ----------------
    for (int i = wid; i < Jn; i += 8) {
        float v0 = sm[OFF_HP2 + i * HDn + lane];
        float v1 = sm[OFF_HP2 + i * HDn + lane + 32];
        float m = warp_max(fmaxf(v0, v1));
        float s = warp_sum(__expf(v0 - m) + __expf(v1 - m));
        float lse = m + __logf(s);
        float* op = out + (long long)pair * (Jn * HDn) + i * HDn;
        op[lane]      = v0 - lse;
        op[lane + 32] = v1 - lse;
    }
}

extern "C" void kernel_launch(void* const* d_in, const int* in_sizes, int n_in,
                              void* d_out, int out_size)
{
    const float* inp = (const float*)d_in[0];
    // d_in[1] = seq_start_end (unused by the reference computation)
    const float* Wh  = (const float*)d_in[2];
    const float* ah  = (const float*)d_in[3];
    const float* Wo  = (const float*)d_in[4];
    const float* ao  = (const float*)d_in[5];
    float* out = (float*)d_out;

    const int npairs = in_sizes[0] / (Jn * NHn);   // 16*1024 = 16384

    cudaFuncSetAttribute(gat_kernel, cudaFuncAttributeMaxDynamicSharedMemorySize, SMEM_BYTES);
    gat_kernel<<<npairs, NTHREADS, SMEM_BYTES>>>(inp, Wh, ah, Wo, ao, out);
}

// round 5
// speedup vs baseline: 2.3443x; 1.3702x over previous
#include <cuda_runtime.h>
#include <math.h>

#define Jn 21
#define NHn 7
#define Hn 4
#define HDn 64
#define NTHREADS 256
#define HPT_LD 24
#define ATT_LD 24

typedef unsigned long long ull;

// ---- shared memory layout (float offsets) ----
constexpr int OFF_H    = 0;                            // 4*21*64 = 5376 (aliased by REDBUF in phase 3)
constexpr int OFF_HPT  = OFF_H + Hn * Jn * HDn;        // 256*24  = 6144
constexpr int OFF_ATTN = OFF_HPT + 256 * HPT_LD;       // 4*21*24 = 2016
constexpr int OFF_XD   = OFF_ATTN + Hn * Jn * ATT_LD;  // 21*8*2  = 336 (dup f2)
constexpr int OFF_F1   = OFF_XD + Jn * 8 * 2;          // 84
constexpr int OFF_F2   = OFF_F1 + Hn * Jn;             // 84
constexpr int OFF_H2   = OFF_F2 + Hn * Jn;             // 21*64 = 1344
constexpr int OFF_HP2  = OFF_H2 + Jn * HDn;            // 1344
constexpr int OFF_F1B  = OFF_HP2 + Jn * HDn;           // 21
constexpr int OFF_F2B  = OFF_F1B + Jn;                 // 21
constexpr int OFF_AT2D = OFF_F2B + Jn;                 // 21*21*2 = 882 (dup f2)
constexpr int SMEM_FLOATS = OFF_AT2D + Jn * Jn * 2;    // 17652
constexpr int SMEM_BYTES  = SMEM_FLOATS * 4;           // ~70.6 KB -> 2 CTAs/SM, L1D keeps W_out

static_assert(OFF_HPT % 4 == 0 && OFF_ATTN % 4 == 0 && OFF_H2 % 4 == 0 && OFF_HP2 % 4 == 0, "align16");
static_assert(OFF_XD % 2 == 0 && OFF_AT2D % 2 == 0, "align8");
static_assert(Hn * Jn * HDn >= 4 * Jn * 32 * 2, "REDBUF fits in H");  // 4 partials * 672 ull

__device__ __forceinline__ void ffma2(ull& d, ull a, ull b) {
    asm("fma.rn.f32x2 %0, %1, %2, %3;" : "=l"(d) : "l"(a), "l"(b), "l"(d));
}
__device__ __forceinline__ void fadd2(ull& d, ull a, ull b) {
    asm("add.rn.f32x2 %0, %1, %2;" : "=l"(d) : "l"(a), "l"(b));
}
__device__ __forceinline__ ull dup2(float x) {
    ull r; unsigned xi = __float_as_uint(x);
    asm("mov.b64 %0, {%1, %1};" : "=l"(r) : "r"(xi));
    return r;
}
__device__ __forceinline__ float2 unpk(ull v) {
    float2 r;
    asm("mov.b64 {%0, %1}, %2;" : "=f"(r.x), "=f"(r.y) : "l"(v));
    return r;
}
__device__ __forceinline__ float warp_sum(float v) {
    #pragma unroll
    for (int o = 16; o > 0; o >>= 1) v += __shfl_xor_sync(0xffffffffu, v, o);
    return v;
}
__device__ __forceinline__ float warp_max(float v) {
    #pragma unroll
    for (int o = 16; o > 0; o >>= 1) v = fmaxf(v, __shfl_xor_sync(0xffffffffu, v, o));
    return v;
}
// reduce two floats across warp simultaneously
__device__ __forceinline__ void warp_sum2(float& a, float& b) {
    #pragma unroll
    for (int o = 16; o > 0; o >>= 1) {
        a += __shfl_xor_sync(0xffffffffu, a, o);
        b += __shfl_xor_sync(0xffffffffu, b, o);
    }
}
__device__ __forceinline__ float elu1(float x) {
    return x > 0.f ? x : (__expf(x) - 1.f);
}

__global__ void __launch_bounds__(NTHREADS, 2)
gat_kernel(const float* __restrict__ inp,
           const float* __restrict__ W_heads,
           const float* __restrict__ a_heads,
           const float* __restrict__ W_out,
           const float* __restrict__ a_out,
           float* __restrict__ out)
{
    extern __shared__ float sm[];
    const int tid  = threadIdx.x;
    const int lane = tid & 31;
    const int wid  = tid >> 5;
    const int pair = blockIdx.x;

    // ---------------- Phase 0: stage x (reshaped, duplicated for f32x2) ----------------
    {
        const float* ip = inp + (long long)pair * (Jn * NHn);
        if (tid < Jn * NHn) {
            float v = ip[tid];
            int j, c;
            if (tid < Jn * 3)          { j = tid / 3;          c = tid % 3; }
            else if (tid < 2 * Jn * 3) { int t = tid - Jn * 3; j = t / 3;  c = 3 + t % 3; }
            else                       { j = tid - 2 * Jn * 3; c = 6; }
            ((float2*)(sm + OFF_XD))[j * 8 + c] = make_float2(v, v);
        }
    }
    __syncthreads();

    // ---------------- Phase 1 (+1b fused): h = x @ W_heads ; f1/f2 via shuffles ----------------
    {
        const int hh = wid >> 1;           // head
        const int jh = wid & 1;            // j-half
        // W, a direct from global (L1-resident, shared across whole chip)
        const ull* wg = (const ull*)W_heads + hh * (NHn * 32) + lane;
        ull w[NHn];
        #pragma unroll
        for (int n = 0; n < NHn; n++) w[n] = __ldg(wg + n * 32);
        const ull a1p = __ldg((const ull*)a_heads + hh * 64 + lane);
        const ull a2p = __ldg((const ull*)a_heads + hh * 64 + 32 + lane);
        const float2 a1f = unpk(a1p), a2f = unpk(a2p);

        const int j0 = jh * 11, cnt = 11 - jh;
        const ull* xd = (const ull*)(sm + OFF_XD);
        ull* hout = (ull*)(sm + OFF_H);
        for (int jj = 0; jj < cnt; jj++) {
            const int j = j0 + jj;
            const ull* xr = xd + j * 8;
            ull acc = 0ull;
            #pragma unroll
            for (int n = 0; n < NHn; n++) ffma2(acc, xr[n], w[n]);
            hout[(hh * Jn + j) * 32 + lane] = acc;
            // fused f1/f2
            float2 hf = unpk(acc);
            float p1 = hf.x * a1f.x + hf.y * a1f.y;
            float p2 = hf.x * a2f.x + hf.y * a2f.y;
            warp_sum2(p1, p2);
            if (lane == 0) {
                sm[OFF_F1 + hh * Jn + j] = p1;
                sm[OFF_F2 + hh * Jn + j] = p2;
            }
        }
    }
    __syncthreads();

    // ---------------- Phase 2a: per-row softmax of leaky_relu(f1_i + f2_j) ----------------
    if (tid < Hn * Jn) {
        const int hh = tid / Jn;
        const float fi = sm[OFF_F1 + tid];
        const float* f2r = sm + OFF_F2 + hh * Jn;
        float ebuf[Jn];
        float m = -1e30f;
        #pragma unroll
        for (int j = 0; j < Jn; j++) {
            float e = fi + f2r[j];
            e = e > 0.f ? e : 0.2f * e;
            ebuf[j] = e;
            m = fmaxf(m, e);
        }
        float s = 0.f;
        #pragma unroll
        for (int j = 0; j < Jn; j++) { float t = __expf(ebuf[j] - m); ebuf[j] = t; s += t; }
        float inv = 1.f / s;
        float* arow = sm + OFF_ATTN + tid * ATT_LD;
        #pragma unroll
        for (int j = 0; j < Jn; j++) arow[j] = ebuf[j] * inv;
    }
    __syncthreads();

    // ---------------- Phase 2b: hp = elu(attn @ h) -> hpT[k][i], h register-cached ----------------
    {
        const int hh = wid >> 1;
        const int ihalf = wid & 1;
        const int i0 = ihalf * 11, cnt = 11 - ihalf;
        // cache this head's h column (d-pair = lane) for all 21 j
        ull hvec[Jn];
        const ull* hbase = (const ull*)(sm + OFF_H) + hh * Jn * 32 + lane;
        #pragma unroll
        for (int j = 0; j < Jn; j++) hvec[j] = hbase[j * 32];

        for (int ii = 0; ii < cnt; ii++) {
            const int i = i0 + ii;
            const float4* at = (const float4*)(sm + OFF_ATTN + (hh * Jn + i) * ATT_LD);
            ull acc = 0ull;
            #pragma unroll
            for (int q = 0; q < 5; q++) {
                float4 a4 = at[q];
                ffma2(acc, dup2(a4.x), hvec[q * 4 + 0]);
                ffma2(acc, dup2(a4.y), hvec[q * 4 + 1]);
                ffma2(acc, dup2(a4.z), hvec[q * 4 + 2]);
                ffma2(acc, dup2(a4.w), hvec[q * 4 + 3]);
            }
            { float a20 = *((const float*)(at + 5)); ffma2(acc, dup2(a20), hvec[20]); }
            float2 e = unpk(acc);
            const int k = hh * HDn + 2 * lane;
            sm[OFF_HPT + k * HPT_LD + i]       = elu1(e.x);
            sm[OFF_HPT + (k + 1) * HPT_LD + i] = elu1(e.y);
        }
    }
    __syncthreads();

    // ---------------- Phase 3: h2 = hp @ W_out (21x256x64), k-split 4 x j-split 2 ----------------
    {
        const int kh = wid >> 1;           // k slice (64 k each)
        const int jg = wid & 1;            // j group: 0 -> j 0..11, 1 -> j 12..20
        const ull* wp = (const ull*)W_out + (kh * 64) * 32 + lane;
        const float* hrow = sm + OFF_HPT + (kh * 64) * HPT_LD + (jg ? 12 : 0);
        ull* RED = (ull*)(sm + OFF_H);     // [4][21][32] partials, aliases dead h

        if (jg == 0) {
            ull acc[12];
            #pragma unroll
            for (int t = 0; t < 12; t++) acc[t] = 0ull;
            #pragma unroll 4
            for (int k = 0; k < 64; k++) {
                ull wv = __ldg(wp); wp += 32;
                float4 h0 = *(const float4*)(hrow);
                float4 h1 = *(const float4*)(hrow + 4);
                float4 h2v = *(const float4*)(hrow + 8);
                hrow += HPT_LD;
                ffma2(acc[0],  dup2(h0.x),  wv); ffma2(acc[1],  dup2(h0.y),  wv);
                ffma2(acc[2],  dup2(h0.z),  wv); ffma2(acc[3],  dup2(h0.w),  wv);
                ffma2(acc[4],  dup2(h1.x),  wv); ffma2(acc[5],  dup2(h1.y),  wv);
                ffma2(acc[6],  dup2(h1.z),  wv); ffma2(acc[7],  dup2(h1.w),  wv);
                ffma2(acc[8],  dup2(h2v.x), wv); ffma2(acc[9],  dup2(h2v.y), wv);
                ffma2(acc[10], dup2(h2v.z), wv); ffma2(acc[11], dup2(h2v.w), wv);
            }
            #pragma unroll
            for (int t = 0; t < 12; t++)
                RED[(kh * Jn + t) * 32 + lane] = acc[t];
        } else {
            ull acc[9];
            #pragma unroll
            for (int t = 0; t < 9; t++) acc[t] = 0ull;
            #pragma unroll 4
            for (int k = 0; k < 64; k++) {
                ull wv = __ldg(wp); wp += 32;
                float4 h0 = *(const float4*)(hrow);
                float4 h1 = *(const float4*)(hrow + 4);
                float s20 = hrow[8];
                hrow += HPT_LD;
                ffma2(acc[0], dup2(h0.x), wv); ffma2(acc[1], dup2(h0.y), wv);
                ffma2(acc[2], dup2(h0.z), wv); ffma2(acc[3], dup2(h0.w), wv);
                ffma2(acc[4], dup2(h1.x), wv); ffma2(acc[5], dup2(h1.y), wv);
                ffma2(acc[6], dup2(h1.z), wv); ffma2(acc[7], dup2(h1.w), wv);
                ffma2(acc[8], dup2(s20),  wv);
            }
            #pragma unroll
            for (int t = 0; t < 9; t++)
                RED[(kh * Jn + 12 + t) * 32 + lane] = acc[t];
        }
    }
    __syncthreads();

    // ---------------- Phase 3r (+4a fused): reduce partials -> h2; f1b/f2b via shuffles ----------------
    {
        const ull* RED = (const ull*)(sm + OFF_H);
        const ull ao1p = __ldg((const ull*)a_out + lane);
        const ull ao2p = __ldg((const ull*)a_out + 32 + lane);
        const float2 ao1 = unpk(ao1p), ao2 = unpk(ao2p);
        ull* h2 = (ull*)(sm + OFF_H2);
        #pragma unroll
        for (int it = 0; it < 3; it++) {
            const int s = tid + it * 256;           // slot = row*32 + lane, row = j
            if (s < Jn * 32) {                      // warp-uniform (672 % 32 == 0)
                ull v = RED[s];
                fadd2(v, v, RED[s + 672]);
                ull v2; fadd2(v2, RED[s + 1344], RED[s + 2016]);
                fadd2(v, v, v2);
                h2[s] = v;
                float2 vf = unpk(v);
                float p1 = vf.x * ao1.x + vf.y * ao1.y;
                float p2 = vf.x * ao2.x + vf.y * ao2.y;
                warp_sum2(p1, p2);
                if (lane == 0) {
                    sm[OFF_F1B + (s >> 5)] = p1;
                    sm[OFF_F2B + (s >> 5)] = p2;
                }
            }
        }
    }
    __syncthreads();

    // ---------------- Phase 4b: second softmax (duplicated store) ----------------
    if (tid < Jn) {
        const float fi = sm[OFF_F1B + tid];
        float ebuf[Jn];
        float m = -1e30f;
        #pragma unroll
        for (int j = 0; j < Jn; j++) {
            float e = fi + sm[OFF_F2B + j];
            e = e > 0.f ? e : 0.2f * e;
            ebuf[j] = e;
            m = fmaxf(m, e);
        }
        float s = 0.f;
        #pragma unroll
        for (int j = 0; j < Jn; j++) { float t = __expf(ebuf[j] - m); ebuf[j] = t; s += t; }
        float inv = 1.f / s;
        #pragma unroll
        for (int j = 0; j < Jn; j++)
            ((float2*)(sm + OFF_AT2D))[tid * Jn + j] = make_float2(ebuf[j] * inv, ebuf[j] * inv);
    }
    __syncthreads();

    // ---------------- Phase 4c: hp2 = elu(attn2 @ h2) ----------------
    for (int u = tid; u < Jn * (HDn / 4); u += NTHREADS) {
        const int dq = u & 15;
        const int i  = u >> 4;
        const ull* ar = (const ull*)(sm + OFF_AT2D) + i * Jn;
        const char* hbytes = (const char*)(sm + OFF_H2 + dq * 4);
        ull acc01 = 0ull, acc23 = 0ull;
        #pragma unroll
        for (int j = 0; j < Jn; j++) {
            ull a2 = ar[j];
            ulonglong2 hv = *(const ulonglong2*)(hbytes + j * (HDn * 4));
            ffma2(acc01, a2, hv.x);
            ffma2(acc23, a2, hv.y);
        }
        float2 e01 = unpk(acc01), e23 = unpk(acc23);
        float4 r;
        r.x = elu1(e01.x); r.y = elu1(e01.y); r.z = elu1(e23.x); r.w = elu1(e23.y);
        *(float4*)(sm + OFF_HP2 + i * HDn + dq * 4) = r;
    }
    __syncthreads();

    // ---------------- Phase 4d: log_softmax over d, write out ----------------
    for (int i = wid; i < Jn; i += 8) {
        float v0 = sm[OFF_HP2 + i * HDn + lane];
        float v1 = sm[OFF_HP2 + i * HDn + lane + 32];
        float m = warp_max(fmaxf(v0, v1));
        float s = warp_sum(__expf(v0 - m) + __expf(v1 - m));
        float lse = m + __logf(s);
        float* op = out + (long long)pair * (Jn * HDn) + i * HDn;
        op[lane]      = v0 - lse;
        op[lane + 32] = v1 - lse;
    }
}

extern "C" void kernel_launch(void* const* d_in, const int* in_sizes, int n_in,
                              void* d_out, int out_size)
{
    const float* inp = (const float*)d_in[0];
    // d_in[1] = seq_start_end (unused by the reference computation)
    const float* Wh  = (const float*)d_in[2];
    const float* ah  = (const float*)d_in[3];
    const float* Wo  = (const float*)d_in[4];
    const float* ao  = (const float*)d_in[5];
    float* out = (float*)d_out;

    const int npairs = in_sizes[0] / (Jn * NHn);   // 16*1024 = 16384

    cudaFuncSetAttribute(gat_kernel, cudaFuncAttributeMaxDynamicSharedMemorySize, SMEM_BYTES);
    gat_kernel<<<npairs, NTHREADS, SMEM_BYTES>>>(inp, Wh, ah, Wo, ao, out);
}

// round 6
// speedup vs baseline: 2.7327x; 1.1657x over previous
#include <cuda_runtime.h>
#include <math.h>

#define Jn 21
#define NHn 7
#define Hn 4
#define HDn 64
#define NTHREADS 256
#define HPT_LD 28
#define ATT_LD 28

typedef unsigned long long ull;

// ---- shared memory layout (float offsets) ----
constexpr int OFF_H    = 0;                              // 4*21*64 = 5376 (alias: RED partials in ph3)
constexpr int OFF_HPT  = OFF_H + Hn * Jn * HDn;          // 256*28  = 7168 (alias: HP2 in ph4c)
constexpr int OFF_ATTN = OFF_HPT + 256 * HPT_LD;         // 4*21*28 = 2352 (alias: AT2 in ph4b)
constexpr int OFF_XD   = OFF_ATTN + Hn * Jn * ATT_LD;    // 21*8*2  = 336 (dup f2)
constexpr int OFF_F1   = OFF_XD + Jn * 8 * 2;            // 84
constexpr int OFF_F2   = OFF_F1 + Hn * Jn;               // 84
constexpr int OFF_H2   = OFF_F2 + Hn * Jn;               // 21*64 = 1344
constexpr int OFF_F1B  = OFF_H2 + Jn * HDn;              // 21
constexpr int OFF_F2B  = OFF_F1B + Jn;                   // 21
constexpr int OFF_HP2  = OFF_HPT;                        // alias (HPT dead after ph3)
constexpr int OFF_AT2  = OFF_ATTN;                       // alias (ATTN dead after ph2b)
constexpr int SMEM_FLOATS = OFF_F2B + Jn;                // 16786
constexpr int SMEM_BYTES  = SMEM_FLOATS * 4;             // ~67.1 KB -> 2 CTAs/SM

static_assert(OFF_HPT % 4 == 0 && OFF_ATTN % 4 == 0 && OFF_H2 % 2 == 0, "align");
static_assert(Hn * Jn * HDn == 4 * Jn * 64, "RED fits H exactly");

__device__ __forceinline__ void ffma2(ull& d, ull a, ull b) {
    asm("fma.rn.f32x2 %0, %1, %2, %3;" : "=l"(d) : "l"(a), "l"(b), "l"(d));
}
__device__ __forceinline__ void fadd2(ull& d, ull a, ull b) {
    asm("add.rn.f32x2 %0, %1, %2;" : "=l"(d) : "l"(a), "l"(b));
}
__device__ __forceinline__ ull dup2(float x) {
    ull r; unsigned xi = __float_as_uint(x);
    asm("mov.b64 %0, {%1, %1};" : "=l"(r) : "r"(xi));
    return r;
}
__device__ __forceinline__ ull pack2(float a, float b) {
    ull r;
    asm("mov.b64 %0, {%1, %2};" : "=l"(r) : "f"(a), "f"(b));
    return r;
}
__device__ __forceinline__ float2 unpk(ull v) {
    float2 r;
    asm("mov.b64 {%0, %1}, %2;" : "=f"(r.x), "=f"(r.y) : "l"(v));
    return r;
}
__device__ __forceinline__ float warp_sum(float v) {
    #pragma unroll
    for (int o = 16; o > 0; o >>= 1) v += __shfl_xor_sync(0xffffffffu, v, o);
    return v;
}
__device__ __forceinline__ float warp_max(float v) {
    #pragma unroll
    for (int o = 16; o > 0; o >>= 1) v = fmaxf(v, __shfl_xor_sync(0xffffffffu, v, o));
    return v;
}
__device__ __forceinline__ void warp_sum2(float& a, float& b) {
    #pragma unroll
    for (int o = 16; o > 0; o >>= 1) {
        a += __shfl_xor_sync(0xffffffffu, a, o);
        b += __shfl_xor_sync(0xffffffffu, b, o);
    }
}
__device__ __forceinline__ float elu1(float x) {
    return x > 0.f ? x : (__expf(x) - 1.f);
}

__global__ void __launch_bounds__(NTHREADS, 2)
gat_kernel(const float* __restrict__ inp,
           const float* __restrict__ W_heads,
           const float* __restrict__ a_heads,
           const float* __restrict__ W_out,
           const float* __restrict__ a_out,
           float* __restrict__ out)
{
    extern __shared__ float sm[];
    const int tid  = threadIdx.x;
    const int lane = tid & 31;
    const int wid  = tid >> 5;
    const int pair = blockIdx.x;

    // ---------------- Phase 0: stage x (reshaped, duplicated for f32x2) ----------------
    {
        const float* ip = inp + (long long)pair * (Jn * NHn);
        if (tid < Jn * NHn) {
            float v = ip[tid];
            int j, c;
            if (tid < Jn * 3)          { j = tid / 3;          c = tid % 3; }
            else if (tid < 2 * Jn * 3) { int t = tid - Jn * 3; j = t / 3;  c = 3 + t % 3; }
            else                       { j = tid - 2 * Jn * 3; c = 6; }
            ((float2*)(sm + OFF_XD))[j * 8 + c] = make_float2(v, v);
        }
    }
    __syncthreads();

    // ---------------- Phase 1 (+1b): h = x @ Wh, packed as (d=lane, d=lane+32) ----------------
    {
        const int hh = wid >> 1;           // head
        const int jh = wid & 1;            // j-half
        const float* wg = W_heads + hh * (NHn * HDn) + lane;
        ull w[NHn];
        #pragma unroll
        for (int n = 0; n < NHn; n++)
            w[n] = pack2(__ldg(wg + n * HDn), __ldg(wg + n * HDn + 32));
        const float2 a1f = make_float2(__ldg(a_heads + hh * 128 + lane),
                                       __ldg(a_heads + hh * 128 + lane + 32));
        const float2 a2f = make_float2(__ldg(a_heads + hh * 128 + 64 + lane),
                                       __ldg(a_heads + hh * 128 + 64 + lane + 32));

        const int j0 = jh * 11, cnt = 11 - jh;
        const ull* xd = (const ull*)(sm + OFF_XD);
        ull* hout = (ull*)(sm + OFF_H);
        for (int jj = 0; jj < cnt; jj++) {
            const int j = j0 + jj;
            const ull* xr = xd + j * 8;
            ull acc = 0ull;
            #pragma unroll
            for (int n = 0; n < NHn; n++) ffma2(acc, xr[n], w[n]);
            hout[(hh * Jn + j) * 32 + lane] = acc;
            float2 hf = unpk(acc);
            float p1 = hf.x * a1f.x + hf.y * a1f.y;
            float p2 = hf.x * a2f.x + hf.y * a2f.y;
            warp_sum2(p1, p2);
            if (lane == 0) {
                sm[OFF_F1 + hh * Jn + j] = p1;
                sm[OFF_F2 + hh * Jn + j] = p2;
            }
        }
    }
    __syncthreads();

    // ---------------- Phase 2a: per-row softmax of leaky_relu(f1_i + f2_j) ----------------
    if (tid < Hn * Jn) {
        const int hh = tid / Jn;
        const float fi = sm[OFF_F1 + tid];
        const float* f2r = sm + OFF_F2 + hh * Jn;
        float ebuf[Jn];
        float m = -1e30f;
        #pragma unroll
        for (int j = 0; j < Jn; j++) {
            float e = fi + f2r[j];
            e = e > 0.f ? e : 0.2f * e;
            ebuf[j] = e;
            m = fmaxf(m, e);
        }
        float s = 0.f;
        #pragma unroll
        for (int j = 0; j < Jn; j++) { float t = __expf(ebuf[j] - m); ebuf[j] = t; s += t; }
        float inv = 1.f / s;
        float* arow = sm + OFF_ATTN + tid * ATT_LD;
        #pragma unroll
        for (int j = 0; j < Jn; j++) arow[j] = ebuf[j] * inv;
    }
    __syncthreads();

    // ---------------- Phase 2b: hp = elu(attn @ h) -> hpT[k][i] (k = hh*64 + d) ----------------
    {
        const int hh = wid >> 1;
        const int ihalf = wid & 1;
        const int i0 = ihalf * 11, cnt = 11 - ihalf;
        ull hvec[Jn];
        const ull* hbase = (const ull*)(sm + OFF_H) + hh * Jn * 32 + lane;
        #pragma unroll
        for (int j = 0; j < Jn; j++) hvec[j] = hbase[j * 32];

        float* row_a = sm + OFF_HPT + (hh * HDn + lane) * HPT_LD;
        float* row_b = row_a + 32 * HPT_LD;
        for (int ii = 0; ii < cnt; ii++) {
            const int i = i0 + ii;
            const float4* at = (const float4*)(sm + OFF_ATTN + (hh * Jn + i) * ATT_LD);
            ull acc = 0ull;
            #pragma unroll
            for (int q = 0; q < 5; q++) {
                float4 a4 = at[q];
                ffma2(acc, dup2(a4.x), hvec[q * 4 + 0]);
                ffma2(acc, dup2(a4.y), hvec[q * 4 + 1]);
                ffma2(acc, dup2(a4.z), hvec[q * 4 + 2]);
                ffma2(acc, dup2(a4.w), hvec[q * 4 + 3]);
            }
            { float a20 = ((const float*)at)[20]; ffma2(acc, dup2(a20), hvec[20]); }
            float2 e = unpk(acc);
            row_a[i] = elu1(e.x);      // lane stride 28 -> 4-way (was 16-way)
            row_b[i] = elu1(e.y);
        }
    }
    __syncthreads();

    // ---------------- Phase 3: h2 = hp @ W_out, packed over j-pairs (dup2 once per k) ----------------
    {
        const int kh = wid >> 1;           // k slice (64 k each)
        const int jg = wid & 1;            // j group
        const float* wp = W_out + (kh * 64) * HDn + lane;
        const float* hrow = sm + OFF_HPT + (kh * 64) * HPT_LD + (jg ? 12 : 0);
        float* RED = sm + OFF_H;           // float view [4][21][64], aliases dead h

        if (jg == 0) {
            ull acc[12];
            #pragma unroll
            for (int t = 0; t < 12; t++) acc[t] = 0ull;
            #pragma unroll 4
            for (int k = 0; k < 64; k++) {
                ull uwa = dup2(__ldg(wp));
                ull uwb = dup2(__ldg(wp + 32));
                wp += HDn;
                ulonglong2 p01 = *(const ulonglong2*)(hrow);       // {j0j1, j2j3}
                ulonglong2 p23 = *(const ulonglong2*)(hrow + 4);   // {j4j5, j6j7}
                ulonglong2 p45 = *(const ulonglong2*)(hrow + 8);   // {j8j9, j10j11}
                hrow += HPT_LD;
                ffma2(acc[0],  p01.x, uwa); ffma2(acc[1],  p01.x, uwb);
                ffma2(acc[2],  p01.y, uwa); ffma2(acc[3],  p01.y, uwb);
                ffma2(acc[4],  p23.x, uwa); ffma2(acc[5],  p23.x, uwb);
                ffma2(acc[6],  p23.y, uwa); ffma2(acc[7],  p23.y, uwb);
                ffma2(acc[8],  p45.x, uwa); ffma2(acc[9],  p45.x, uwb);
                ffma2(acc[10], p45.y, uwa); ffma2(acc[11], p45.y, uwb);
            }
            #pragma unroll
            for (int q = 0; q < 6; q++) {
                float2 va = unpk(acc[2 * q]);      // {out[2q][la], out[2q+1][la]}
                float2 vb = unpk(acc[2 * q + 1]);
                RED[(kh * Jn + 2 * q) * 64 + lane]          = va.x;
                RED[(kh * Jn + 2 * q + 1) * 64 + lane]      = va.y;
                RED[(kh * Jn + 2 * q) * 64 + lane + 32]     = vb.x;
                RED[(kh * Jn + 2 * q + 1) * 64 + lane + 32] = vb.y;
            }
        } else {
            ull acc[8];
            #pragma unroll
            for (int t = 0; t < 8; t++) acc[t] = 0ull;
            float a20a = 0.f, a20b = 0.f;
            #pragma unroll 4
            for (int k = 0; k < 64; k++) {
                float wa = __ldg(wp), wb = __ldg(wp + 32);
                wp += HDn;
                ull uwa = dup2(wa), uwb = dup2(wb);
                ulonglong2 p01 = *(const ulonglong2*)(hrow);       // {j12j13, j14j15}
                ulonglong2 p23 = *(const ulonglong2*)(hrow + 4);   // {j16j17, j18j19}
                float h20 = hrow[8];
                hrow += HPT_LD;
                ffma2(acc[0], p01.x, uwa); ffma2(acc[1], p01.x, uwb);
                ffma2(acc[2], p01.y, uwa); ffma2(acc[3], p01.y, uwb);
                ffma2(acc[4], p23.x, uwa); ffma2(acc[5], p23.x, uwb);
                ffma2(acc[6], p23.y, uwa); ffma2(acc[7], p23.y, uwb);
                a20a = fmaf(h20, wa, a20a);
                a20b = fmaf(h20, wb, a20b);
            }
            #pragma unroll
            for (int q = 0; q < 4; q++) {
                float2 va = unpk(acc[2 * q]);
                float2 vb = unpk(acc[2 * q + 1]);
                RED[(kh * Jn + 12 + 2 * q) * 64 + lane]          = va.x;
                RED[(kh * Jn + 12 + 2 * q + 1) * 64 + lane]      = va.y;
                RED[(kh * Jn + 12 + 2 * q) * 64 + lane + 32]     = vb.x;
                RED[(kh * Jn + 12 + 2 * q + 1) * 64 + lane + 32] = vb.y;
            }
            RED[(kh * Jn + 20) * 64 + lane]      = a20a;
            RED[(kh * Jn + 20) * 64 + lane + 32] = a20b;
        }
    }
    __syncthreads();

    // ---------------- Phase 3r (+4a): reduce partials -> h2; f1b/f2b via shuffles ----------------
    {
        const ull* RED = (const ull*)(sm + OFF_H);   // [4][672] ull
        const float2 ao1 = make_float2(__ldg(a_out + 2 * lane), __ldg(a_out + 2 * lane + 1));
        const float2 ao2 = make_float2(__ldg(a_out + 64 + 2 * lane), __ldg(a_out + 64 + 2 * lane + 1));
        ull* h2 = (ull*)(sm + OFF_H2);
        #pragma unroll
        for (int it = 0; it < 3; it++) {
            const int s = tid + it * 256;           // slot = j*32 + t
            if (s < Jn * 32) {                      // warp-uniform (672 % 32 == 0)
                ull v = RED[s];
                fadd2(v, v, RED[s + 672]);
                ull v2; fadd2(v2, RED[s + 1344], RED[s + 2016]);
                fadd2(v, v, v2);
                h2[s] = v;
                float2 vf = unpk(v);
                float p1 = vf.x * ao1.x + vf.y * ao1.y;
                float p2 = vf.x * ao2.x + vf.y * ao2.y;
                warp_sum2(p1, p2);
                if (lane == 0) {
                    sm[OFF_F1B + (s >> 5)] = p1;
                    sm[OFF_F2B + (s >> 5)] = p2;
                }
            }
        }
    }
    __syncthreads();

    // ---------------- Phase 4b: second softmax -> AT2 (aliases ATTN) ----------------
    if (tid < Jn) {
        const float fi = sm[OFF_F1B + tid];
        float ebuf[Jn];
        float m = -1e30f;
        #pragma unroll
        for (int j = 0; j < Jn; j++) {
            float e = fi + sm[OFF_F2B + j];
            e = e > 0.f ? e : 0.2f * e;
            ebuf[j] = e;
            m = fmaxf(m, e);
        }
        float s = 0.f;
        #pragma unroll
        for (int j = 0; j < Jn; j++) { float t = __expf(ebuf[j] - m); ebuf[j] = t; s += t; }
        float inv = 1.f / s;
        float* arow = sm + OFF_AT2 + tid * ATT_LD;
        #pragma unroll
        for (int j = 0; j < Jn; j++) arow[j] = ebuf[j] * inv;
    }
    __syncthreads();

    // ---------------- Phase 4c: hp2 = elu(attn2 @ h2), h2 register-cached ----------------
    {
        ull h2v[Jn];
        const ull* h2b = (const ull*)(sm + OFF_H2) + lane;
        #pragma unroll
        for (int j = 0; j < Jn; j++) h2v[j] = h2b[j * 32];
        ull* hp2 = (ull*)(sm + OFF_HP2);
        for (int i = wid; i < Jn; i += 8) {
            const float4* at = (const float4*)(sm + OFF_AT2 + i * ATT_LD);
            ull acc = 0ull;
            #pragma unroll
            for (int q = 0; q < 5; q++) {
                float4 a4 = at[q];
                ffma2(acc, dup2(a4.x), h2v[q * 4 + 0]);
                ffma2(acc, dup2(a4.y), h2v[q * 4 + 1]);
                ffma2(acc, dup2(a4.z), h2v[q * 4 + 2]);
                ffma2(acc, dup2(a4.w), h2v[q * 4 + 3]);
            }
            { float a20 = ((const float*)at)[20]; ffma2(acc, dup2(a20), h2v[20]); }
            float2 e = unpk(acc);
            hp2[i * 32 + lane] = pack2(elu1(e.x), elu1(e.y));
        }
    }
    __syncthreads();

    // ---------------- Phase 4d: log_softmax over d, write out ----------------
    for (int i = wid; i < Jn; i += 8) {
        float v0 = sm[OFF_HP2 + i * HDn + lane];
        float v1 = sm[OFF_HP2 + i * HDn + lane + 32];
        float m = warp_max(fmaxf(v0, v1));
        float s = warp_sum(__expf(v0 - m) + __expf(v1 - m));
        float lse = m + __logf(s);
        float* op = out + (long long)pair * (Jn * HDn) + i * HDn;
        op[lane]      = v0 - lse;
        op[lane + 32] = v1 - lse;
    }
}

extern "C" void kernel_launch(void* const* d_in, const int* in_sizes, int n_in,
                              void* d_out, int out_size)
{
    const float* inp = (const float*)d_in[0];
    // d_in[1] = seq_start_end (unused by the reference computation)
    const float* Wh  = (const float*)d_in[2];
    const float* ah  = (const float*)d_in[3];
    const float* Wo  = (const float*)d_in[4];
    const float* ao  = (const float*)d_in[5];
    float* out = (float*)d_out;

    const int npairs = in_sizes[0] / (Jn * NHn);   // 16*1024 = 16384

    cudaFuncSetAttribute(gat_kernel, cudaFuncAttributeMaxDynamicSharedMemorySize, SMEM_BYTES);
    gat_kernel<<<npairs, NTHREADS, SMEM_BYTES>>>(inp, Wh, ah, Wo, ao, out);
}

// round 8
// speedup vs baseline: 2.8857x; 1.0560x over previous
#include <cuda_runtime.h>
#include <math.h>

#define Jn 21
#define NHn 7
#define Hn 4
#define HDn 64
#define NTHREADS 256
#define HPT_LD 28
#define ATT_LD 28

typedef unsigned long long ull;

// ---- shared memory layout (float offsets) ----
constexpr int OFF_H    = 0;                              // 4*21*64 = 5376 (alias: RED partials in ph3)
constexpr int OFF_HPT  = OFF_H + Hn * Jn * HDn;          // 256*28  = 7168 (alias: HP2 in ph4c)
constexpr int OFF_ATTN = OFF_HPT + 256 * HPT_LD;         // 4*21*28 = 2352 (alias: AT2 in ph4b)
constexpr int OFF_XD   = OFF_ATTN + Hn * Jn * ATT_LD;    // 21*8*2  = 336 (dup f2)
constexpr int OFF_F1   = OFF_XD + Jn * 8 * 2;            // 84
constexpr int OFF_F2   = OFF_F1 + Hn * Jn;               // 84
constexpr int OFF_H2   = OFF_F2 + Hn * Jn;               // 21*64 = 1344
constexpr int OFF_F1B  = OFF_H2 + Jn * HDn;              // 21
constexpr int OFF_F2B  = OFF_F1B + Jn;                   // 21
constexpr int OFF_HP2  = OFF_HPT;                        // alias (HPT dead after ph3)
constexpr int OFF_AT2  = OFF_ATTN;                       // alias (ATTN dead after ph2b)
constexpr int SMEM_FLOATS = OFF_F2B + Jn;                // 16786
constexpr int SMEM_BYTES  = SMEM_FLOATS * 4;             // ~67.1 KB -> 2 CTAs/SM

static_assert(OFF_HPT % 4 == 0 && OFF_ATTN % 4 == 0 && OFF_XD % 4 == 0, "align16");
static_assert(Hn * Jn * HDn == 4 * Jn * 64, "RED fits H exactly");

__device__ __forceinline__ void ffma2(ull& d, ull a, ull b) {
    asm("fma.rn.f32x2 %0, %1, %2, %3;" : "=l"(d) : "l"(a), "l"(b), "l"(d));
}
__device__ __forceinline__ void fadd2(ull& d, ull a, ull b) {
    asm("add.rn.f32x2 %0, %1, %2;" : "=l"(d) : "l"(a), "l"(b));
}
__device__ __forceinline__ ull dup2(float x) {
    ull r; unsigned xi = __float_as_uint(x);
    asm("mov.b64 %0, {%1, %1};" : "=l"(r) : "r"(xi));
    return r;
}
__device__ __forceinline__ ull pack2(float a, float b) {
    ull r;
    asm("mov.b64 %0, {%1, %2};" : "=l"(r) : "f"(a), "f"(b));
    return r;
}
__device__ __forceinline__ float2 unpk(ull v) {
    float2 r;
    asm("mov.b64 {%0, %1}, %2;" : "=f"(r.x), "=f"(r.y) : "l"(v));
    return r;
}
__device__ __forceinline__ float warp_sum(float v) {
    #pragma unroll
    for (int o = 16; o > 0; o >>= 1) v += __shfl_xor_sync(0xffffffffu, v, o);
    return v;
}
__device__ __forceinline__ float warp_max(float v) {
    #pragma unroll
    for (int o = 16; o > 0; o >>= 1) v = fmaxf(v, __shfl_xor_sync(0xffffffffu, v, o));
    return v;
}
__device__ __forceinline__ void warp_sum2(float& a, float& b) {
    #pragma unroll
    for (int o = 16; o > 0; o >>= 1) {
        a += __shfl_xor_sync(0xffffffffu, a, o);
        b += __shfl_xor_sync(0xffffffffu, b, o);
    }
}
__device__ __forceinline__ float elu1(float x) {
    return x > 0.f ? x : (__expf(x) - 1.f);
}

__global__ void __launch_bounds__(NTHREADS, 2)
gat_kernel(const float* __restrict__ inp,
           const float* __restrict__ W_heads,
           const float* __restrict__ a_heads,
           const float* __restrict__ W_out,
           const float* __restrict__ a_out,
           float* __restrict__ out)
{
    extern __shared__ float sm[];
    const int tid  = threadIdx.x;
    const int lane = tid & 31;
    const int wid  = tid >> 5;
    const int pair = blockIdx.x;

    // ---------------- Phase 0: stage x (reshaped, duplicated for f32x2) ----------------
    {
        const float* ip = inp + (long long)pair * (Jn * NHn);
        if (tid < Jn * NHn) {
            float v = ip[tid];
            int j, c;
            if (tid < Jn * 3)          { j = tid / 3;          c = tid % 3; }
            else if (tid < 2 * Jn * 3) { int t = tid - Jn * 3; j = t / 3;  c = 3 + t % 3; }
            else                       { j = tid - 2 * Jn * 3; c = 6; }
            ((float2*)(sm + OFF_XD))[j * 8 + c] = make_float2(v, v);
        }
        if (tid < Jn)   // zero pad slot c=7 (read by float4 path, value unused but keep defined)
            ((float2*)(sm + OFF_XD))[tid * 8 + 7] = make_float2(0.f, 0.f);
    }
    __syncthreads();

    // ---------------- Phase 1 (+1b): h = x @ Wh ; f1/f2 = x @ (Wh@a) (no per-j reduction) ----------------
    {
        const int hh = wid >> 1;           // head
        const int jh = wid & 1;            // j-half
        const float* wg = W_heads + hh * (NHn * HDn) + lane;
        ull w[NHn];
        #pragma unroll
        for (int n = 0; n < NHn; n++)
            w[n] = pack2(__ldg(wg + n * HDn), __ldg(wg + n * HDn + 32));
        const float2 a1f = make_float2(__ldg(a_heads + hh * 128 + lane),
                                       __ldg(a_heads + hh * 128 + lane + 32));
        const float2 a2f = make_float2(__ldg(a_heads + hh * 128 + 64 + lane),
                                       __ldg(a_heads + hh * 128 + 64 + lane + 32));
        // wa1[n] = sum_d Wh[n][d]*a1[d], wa2 likewise (one reduction per n, result in all lanes)
        float wa1[NHn], wa2[NHn];
        #pragma unroll
        for (int n = 0; n < NHn; n++) {
            float2 wf = unpk(w[n]);
            float p1 = wf.x * a1f.x + wf.y * a1f.y;
            float p2 = wf.x * a2f.x + wf.y * a2f.y;
            warp_sum2(p1, p2);
            wa1[n] = p1; wa2[n] = p2;
        }

        const int j0 = jh * 11, cnt = 11 - jh;
        const ulonglong2* xd2 = (const ulonglong2*)(sm + OFF_XD);
        ull* hout = (ull*)(sm + OFF_H);
        for (int jj = 0; jj < cnt; jj++) {
            const int j = j0 + jj;
            ulonglong2 x01 = xd2[j * 4 + 0];
            ulonglong2 x23 = xd2[j * 4 + 1];
            ulonglong2 x45 = xd2[j * 4 + 2];
            ulonglong2 x67 = xd2[j * 4 + 3];   // .y is pad
            ull acc = 0ull;
            ffma2(acc, x01.x, w[0]); ffma2(acc, x01.y, w[1]);
            ffma2(acc, x23.x, w[2]); ffma2(acc, x23.y, w[3]);
            ffma2(acc, x45.x, w[4]); ffma2(acc, x45.y, w[5]);
            ffma2(acc, x67.x, w[6]);
            hout[(hh * Jn + j) * 32 + lane] = acc;
            if (lane == 0) {
                float xs0 = unpk(x01.x).x, xs1 = unpk(x01.y).x;
                float xs2 = unpk(x23.x).x, xs3 = unpk(x23.y).x;
                float xs4 = unpk(x45.x).x, xs5 = unpk(x45.y).x;
                float xs6 = unpk(x67.x).x;
                float f1 = xs0 * wa1[0] + xs1 * wa1[1] + xs2 * wa1[2] + xs3 * wa1[3]
                         + xs4 * wa1[4] + xs5 * wa1[5] + xs6 * wa1[6];
                float f2 = xs0 * wa2[0] + xs1 * wa2[1] + xs2 * wa2[2] + xs3 * wa2[3]
                         + xs4 * wa2[4] + xs5 * wa2[5] + xs6 * wa2[6];
                sm[OFF_F1 + hh * Jn + j] = f1;
                sm[OFF_F2 + hh * Jn + j] = f2;
            }
        }
    }
    __syncthreads();

    // ---------------- Phase 2a: per-row softmax of leaky_relu(f1_i + f2_j) ----------------
    if (tid < Hn * Jn) {
        const int hh = tid / Jn;
        const float fi = sm[OFF_F1 + tid];
        const float* f2r = sm + OFF_F2 + hh * Jn;
        float ebuf[Jn];
        float m = -1e30f;
        #pragma unroll
        for (int j = 0; j < Jn; j++) {
            float e = fi + f2r[j];
            e = e > 0.f ? e : 0.2f * e;
            ebuf[j] = e;
            m = fmaxf(m, e);
        }
        float s = 0.f;
        #pragma unroll
        for (int j = 0; j < Jn; j++) { float t = __expf(ebuf[j] - m); ebuf[j] = t; s += t; }
        float inv = 1.f / s;
        float* arow = sm + OFF_ATTN + tid * ATT_LD;
        #pragma unroll
        for (int j = 0; j < Jn; j++) arow[j] = ebuf[j] * inv;
    }
    __syncthreads();

    // ---------------- Phase 2b: hp = elu(attn @ h) -> hpT[k][i], i-paired STS.64 ----------------
    {
        const int hh = wid >> 1;
        const int ihalf = wid & 1;
        ull hvec[Jn];
        const ull* hbase = (const ull*)(sm + OFF_H) + hh * Jn * 32 + lane;
        #pragma unroll
        for (int j = 0; j < Jn; j++) hvec[j] = hbase[j * 32];

        float* row_a = sm + OFF_HPT + (hh * HDn + lane) * HPT_LD;
        float* row_b = row_a + 32 * HPT_LD;
        const int i0 = ihalf ? 12 : 0;
        const int npair = ihalf ? 4 : 6;
        for (int p = 0; p < npair; p++) {
            const int i = i0 + 2 * p;
            const float4* at0 = (const float4*)(sm + OFF_ATTN + (hh * Jn + i) * ATT_LD);
            const float4* at1 = (const float4*)(sm + OFF_ATTN + (hh * Jn + i + 1) * ATT_LD);
            ull acc0 = 0ull, acc1 = 0ull;
            #pragma unroll
            for (int q = 0; q < 5; q++) {
                float4 a4 = at0[q];
                ffma2(acc0, dup2(a4.x), hvec[q * 4 + 0]);
                ffma2(acc0, dup2(a4.y), hvec[q * 4 + 1]);
                ffma2(acc0, dup2(a4.z), hvec[q * 4 + 2]);
                ffma2(acc0, dup2(a4.w), hvec[q * 4 + 3]);
                float4 b4 = at1[q];
                ffma2(acc1, dup2(b4.x), hvec[q * 4 + 0]);
                ffma2(acc1, dup2(b4.y), hvec[q * 4 + 1]);
                ffma2(acc1, dup2(b4.z), hvec[q * 4 + 2]);
                ffma2(acc1, dup2(b4.w), hvec[q * 4 + 3]);
            }
            { float a20 = ((const float*)at0)[20]; ffma2(acc0, dup2(a20), hvec[20]); }
            { float b20 = ((const float*)at1)[20]; ffma2(acc1, dup2(b20), hvec[20]); }
            float2 e0 = unpk(acc0), e1 = unpk(acc1);
            *(float2*)(row_a + i) = make_float2(elu1(e0.x), elu1(e1.x));
            *(float2*)(row_b + i) = make_float2(elu1(e0.y), elu1(e1.y));
        }
        if (ihalf) {   // i = 20
            const float4* at0 = (const float4*)(sm + OFF_ATTN + (hh * Jn + 20) * ATT_LD);
            ull acc0 = 0ull;
            #pragma unroll
            for (int q = 0; q < 5; q++) {
                float4 a4 = at0[q];
                ffma2(acc0, dup2(a4.x), hvec[q * 4 + 0]);
                ffma2(acc0, dup2(a4.y), hvec[q * 4 + 1]);
                ffma2(acc0, dup2(a4.z), hvec[q * 4 + 2]);
                ffma2(acc0, dup2(a4.w), hvec[q * 4 + 3]);
            }
            { float a20 = ((const float*)at0)[20]; ffma2(acc0, dup2(a20), hvec[20]); }
            float2 e0 = unpk(acc0);
            row_a[20] = elu1(e0.x);
            row_b[20] = elu1(e0.y);
        }
    }
    __syncthreads();

    // ---------------- Phase 3: h2 = hp @ W_out, 8 k-slices x all 21 j, W lines read once ----------------
    {
        const int kh = wid;                // 32 k per warp
        const float* wp = W_out + (kh * 32) * HDn + lane;
        const float* hrow = sm + OFF_HPT + (kh * 32) * HPT_LD;
        ull acc[10][2];
        #pragma unroll
        for (int q = 0; q < 10; q++) { acc[q][0] = 0ull; acc[q][1] = 0ull; }
        float a20a = 0.f, a20b = 0.f;
        #pragma unroll 4
        for (int k = 0; k < 32; k++) {
            float wa = __ldg(wp), wb = __ldg(wp + 32);
            wp += HDn;
            ull uwa = dup2(wa), uwb = dup2(wb);
            ulonglong2 p0 = *(const ulonglong2*)(hrow);        // j0..3
            ulonglong2 p1 = *(const ulonglong2*)(hrow + 4);    // j4..7
            ulonglong2 p2 = *(const ulonglong2*)(hrow + 8);    // j8..11
            ulonglong2 p3 = *(const ulonglong2*)(hrow + 12);   // j12..15
            ulonglong2 p4 = *(const ulonglong2*)(hrow + 16);   // j16..19
            float h20 = hrow[20];
            hrow += HPT_LD;
            ffma2(acc[0][0], p0.x, uwa); ffma2(acc[0][1], p0.x, uwb);
            ffma2(acc[1][0], p0.y, uwa); ffma2(acc[1][1], p0.y, uwb);
            ffma2(acc[2][0], p1.x, uwa); ffma2(acc[2][1], p1.x, uwb);
            ffma2(acc[3][0], p1.y, uwa); ffma2(acc[3][1], p1.y, uwb);
            ffma2(acc[4][0], p2.x, uwa); ffma2(acc[4][1], p2.x, uwb);
            ffma2(acc[5][0], p2.y, uwa); ffma2(acc[5][1], p2.y, uwb);
            ffma2(acc[6][0], p3.x, uwa); ffma2(acc[6][1], p3.x, uwb);
            ffma2(acc[7][0], p3.y, uwa); ffma2(acc[7][1], p3.y, uwb);
            ffma2(acc[8][0], p4.x, uwa); ffma2(acc[8][1], p4.x, uwb);
            ffma2(acc[9][0], p4.y, uwa); ffma2(acc[9][1], p4.y, uwb);
            a20a = fmaf(h20, wa, a20a);
            a20b = fmaf(h20, wb, a20b);
        }

        // Stage A: warps 0-3 store their slices to RED (aliases dead h)
        if (wid < 4) {
            float* RED = sm + OFF_H + wid * (Jn * HDn);
            #pragma unroll
            for (int q = 0; q < 10; q++) {
                float2 va = unpk(acc[q][0]);
                float2 vb = unpk(acc[q][1]);
                RED[(2 * q) * 64 + lane]          = va.x;
                RED[(2 * q + 1) * 64 + lane]      = va.y;
                RED[(2 * q) * 64 + lane + 32]     = vb.x;
                RED[(2 * q + 1) * 64 + lane + 32] = vb.y;
            }
            RED[20 * 64 + lane]      = a20a;
            RED[20 * 64 + lane + 32] = a20b;
        }
        __syncthreads();
        // Stage B: warps 4-7 add in place
        if (wid >= 4) {
            float* RED = sm + OFF_H + (wid - 4) * (Jn * HDn);
            #pragma unroll
            for (int q = 0; q < 10; q++) {
                float2 va = unpk(acc[q][0]);
                float2 vb = unpk(acc[q][1]);
                RED[(2 * q) * 64 + lane]          += va.x;
                RED[(2 * q + 1) * 64 + lane]      += va.y;
                RED[(2 * q) * 64 + lane + 32]     += vb.x;
                RED[(2 * q + 1) * 64 + lane + 32] += vb.y;
            }
            RED[20 * 64 + lane]      += a20a;
            RED[20 * 64 + lane + 32] += a20b;
        }
    }
    __syncthreads();

    // ---------------- Phase 3r (+4a): reduce 4 slices -> h2; f1b/f2b via shuffles ----------------
    {
        const ull* RED = (const ull*)(sm + OFF_H);   // [4][672] ull (consecutive-d pairs)
        const float2 ao1 = make_float2(__ldg(a_out + 2 * lane), __ldg(a_out + 2 * lane + 1));
        const float2 ao2 = make_float2(__ldg(a_out + 64 + 2 * lane), __ldg(a_out + 64 + 2 * lane + 1));
        ull* h2 = (ull*)(sm + OFF_H2);
        #pragma unroll
        for (int it = 0; it < 3; it++) {
            const int s = tid + it * 256;           // slot = j*32 + t
            if (s < Jn * 32) {                      // warp-uniform (672 % 32 == 0)
                ull v = RED[s];
                fadd2(v, v, RED[s + 672]);
                ull v2; fadd2(v2, RED[s + 1344], RED[s + 2016]);
                fadd2(v, v, v2);
                h2[s] = v;
                float2 vf = unpk(v);
                float p1 = vf.x * ao1.x + vf.y * ao1.y;
                float p2 = vf.x * ao2.x + vf.y * ao2.y;
                warp_sum2(p1, p2);
                if (lane == 0) {
                    sm[OFF_F1B + (s >> 5)] = p1;
                    sm[OFF_F2B + (s >> 5)] = p2;
                }
            }
        }
    }
    __syncthreads();

    // ---------------- Phase 4b: second softmax -> AT2 (aliases ATTN) ----------------
    if (tid < Jn) {
        const float fi = sm[OFF_F1B + tid];
        float ebuf[Jn];
        float m = -1e30f;
        #pragma unroll
        for (int j = 0; j < Jn; j++) {
            float e = fi + sm[OFF_F2B + j];
            e = e > 0.f ? e : 0.2f * e;
            ebuf[j] = e;
            m = fmaxf(m, e);
        }
        float s = 0.f;
        #pragma unroll
        for (int j = 0; j < Jn; j++) { float t = __expf(ebuf[j] - m); ebuf[j] = t; s += t; }
        float inv = 1.f / s;
        float* arow = sm + OFF_AT2 + tid * ATT_LD;
        #pragma unroll
        for (int j = 0; j < Jn; j++) arow[j] = ebuf[j] * inv;
    }
    __syncthreads();

    // ---------------- Phase 4c: hp2 = elu(attn2 @ h2), h2 register-cached ----------------
    {
        ull h2v[Jn];
        const ull* h2b = (const ull*)(sm + OFF_H2) + lane;
        #pragma unroll
        for (int j = 0; j < Jn; j++) h2v[j] = h2b[j * 32];
        ull* hp2 = (ull*)(sm + OFF_HP2);
        for (int i = wid; i < Jn; i += 8) {
            const float4* at = (const float4*)(sm + OFF_AT2 + i * ATT_LD);
            ull acc = 0ull;
            #pragma unroll
            for (int q = 0; q < 5; q++) {
                float4 a4 = at[q];
                ffma2(acc, dup2(a4.x), h2v[q * 4 + 0]);
                ffma2(acc, dup2(a4.y), h2v[q * 4 + 1]);
                ffma2(acc, dup2(a4.z), h2v[q * 4 + 2]);
                ffma2(acc, dup2(a4.w), h2v[q * 4 + 3]);
            }
            { float a20 = ((const float*)at)[20]; ffma2(acc, dup2(a20), h2v[20]); }
            float2 e = unpk(acc);
            hp2[i * 32 + lane] = pack2(elu1(e.x), elu1(e.y));
        }
    }
    __syncthreads();

    // ---------------- Phase 4d: log_softmax over d, write out ----------------
    // hp2 rows are consecutive-d pairs: hp2[i*64 + 2*lane], [.. + 2*lane + 1]
    for (int i = wid; i < Jn; i += 8) {
        float2 v = unpk(((const ull*)(sm + OFF_HP2))[i * 32 + lane]);
        float m = warp_max(fmaxf(v.x, v.y));
        float s = warp_sum(__expf(v.x - m) + __expf(v.y - m));
        float lse = m + __logf(s);
        float* op = out + (long long)pair * (Jn * HDn) + i * HDn;
        op[2 * lane]     = v.x - lse;
        op[2 * lane + 1] = v.y - lse;
    }
}

extern "C" void kernel_launch(void* const* d_in, const int* in_sizes, int n_in,
                              void* d_out, int out_size)
{
    const float* inp = (const float*)d_in[0];
    // d_in[1] = seq_start_end (unused by the reference computation)
    const float* Wh  = (const float*)d_in[2];
    const float* ah  = (const float*)d_in[3];
    const float* Wo  = (const float*)d_in[4];
    const float* ao  = (const float*)d_in[5];
    float* out = (float*)d_out;

    const int npairs = in_sizes[0] / (Jn * NHn);   // 16*1024 = 16384

    cudaFuncSetAttribute(gat_kernel, cudaFuncAttributeMaxDynamicSharedMemorySize, SMEM_BYTES);
    gat_kernel<<<npairs, NTHREADS, SMEM_BYTES>>>(inp, Wh, ah, Wo, ao, out);
}

// round 10
// speedup vs baseline: 3.1245x; 1.0828x over previous
#include <cuda_runtime.h>
#include <math.h>

#define Jn 21
#define NHn 7
#define Hn 4
#define HDn 64
#define NTHREADS 256
#define HPT_LD 28
#define ATT_LD 28

typedef unsigned long long ull;

// ---- shared memory layout (float offsets) ----
constexpr int OFF_H    = 0;                              // 4*21*64 = 5376 (alias: RED partials in ph3)
constexpr int OFF_HPT  = OFF_H + Hn * Jn * HDn;          // 256*28  = 7168
constexpr int OFF_ATTN = OFF_HPT + 256 * HPT_LD;         // 4*21*28 = 2352 (alias: AT2 in ph4b)
constexpr int OFF_XD   = OFF_ATTN + Hn * Jn * ATT_LD;    // 21*8*2  = 336 (dup f2)
constexpr int OFF_F1   = OFF_XD + Jn * 8 * 2;            // 84
constexpr int OFF_F2   = OFF_F1 + Hn * Jn;               // 84
constexpr int OFF_H2   = OFF_F2 + Hn * Jn;               // 21*64 = 1344
constexpr int OFF_F1B  = OFF_H2 + Jn * HDn;              // 21
constexpr int OFF_F2B  = OFF_F1B + Jn;                   // 21
constexpr int OFF_AT2  = OFF_ATTN;                       // alias (ATTN dead after ph2b)
constexpr int SMEM_FLOATS = OFF_F2B + Jn;                // 16786
constexpr int SMEM_BYTES  = SMEM_FLOATS * 4;             // ~67.1 KB -> 2 CTAs/SM

static_assert(OFF_HPT % 4 == 0 && OFF_ATTN % 4 == 0 && OFF_XD % 4 == 0, "align16");
static_assert(Hn * Jn * HDn == 4 * Jn * 64, "RED fits H exactly");

__device__ __forceinline__ void ffma2(ull& d, ull a, ull b) {
    asm("fma.rn.f32x2 %0, %1, %2, %3;" : "=l"(d) : "l"(a), "l"(b), "l"(d));
}
__device__ __forceinline__ void fadd2(ull& d, ull a, ull b) {
    asm("add.rn.f32x2 %0, %1, %2;" : "=l"(d) : "l"(a), "l"(b));
}
__device__ __forceinline__ ull dup2(float x) {
    ull r; unsigned xi = __float_as_uint(x);
    asm("mov.b64 %0, {%1, %1};" : "=l"(r) : "r"(xi));
    return r;
}
__device__ __forceinline__ ull pack2(float a, float b) {
    ull r;
    asm("mov.b64 %0, {%1, %2};" : "=l"(r) : "f"(a), "f"(b));
    return r;
}
__device__ __forceinline__ float2 unpk(ull v) {
    float2 r;
    asm("mov.b64 {%0, %1}, %2;" : "=f"(r.x), "=f"(r.y) : "l"(v));
    return r;
}
__device__ __forceinline__ float warp_sum(float v) {
    #pragma unroll
    for (int o = 16; o > 0; o >>= 1) v += __shfl_xor_sync(0xffffffffu, v, o);
    return v;
}
__device__ __forceinline__ float warp_max(float v) {
    #pragma unroll
    for (int o = 16; o > 0; o >>= 1) v = fmaxf(v, __shfl_xor_sync(0xffffffffu, v, o));
    return v;
}
__device__ __forceinline__ void warp_sum2(float& a, float& b) {
    #pragma unroll
    for (int o = 16; o > 0; o >>= 1) {
        a += __shfl_xor_sync(0xffffffffu, a, o);
        b += __shfl_xor_sync(0xffffffffu, b, o);
    }
}
__device__ __forceinline__ float elu1(float x) {
    return x > 0.f ? x : (__expf(x) - 1.f);
}

// one attention row (21 coeffs, broadcast) dotted against 21 register-held packed vectors
__device__ __forceinline__ ull att_dot(const float* atp, const ull* hv) {
    const float4* at = (const float4*)atp;
    ull acc = 0ull;
    #pragma unroll
    for (int q = 0; q < 5; q++) {
        float4 a4 = at[q];
        ffma2(acc, dup2(a4.x), hv[q * 4 + 0]);
        ffma2(acc, dup2(a4.y), hv[q * 4 + 1]);
        ffma2(acc, dup2(a4.z), hv[q * 4 + 2]);
        ffma2(acc, dup2(a4.w), hv[q * 4 + 3]);
    }
    ffma2(acc, dup2(atp[20]), hv[20]);
    return acc;
}

__global__ void __launch_bounds__(NTHREADS, 2)
gat_kernel(const float* __restrict__ inp,
           const float* __restrict__ W_heads,
           const float* __restrict__ a_heads,
           const float* __restrict__ W_out,
           const float* __restrict__ a_out,
           float* __restrict__ out)
{
    extern __shared__ float sm[];
    const int tid  = threadIdx.x;
    const int lane = tid & 31;
    const int wid  = tid >> 5;
    const int pair = blockIdx.x;

    // ---------------- Phase 0: stage x (reshaped, duplicated for f32x2) ----------------
    {
        const float* ip = inp + (long long)pair * (Jn * NHn);
        if (tid < Jn * NHn) {
            float v = ip[tid];
            int j, c;
            if (tid < Jn * 3)          { j = tid / 3;          c = tid % 3; }
            else if (tid < 2 * Jn * 3) { int t = tid - Jn * 3; j = t / 3;  c = 3 + t % 3; }
            else                       { j = tid - 2 * Jn * 3; c = 6; }
            ((float2*)(sm + OFF_XD))[j * 8 + c] = make_float2(v, v);
        }
        if (tid < Jn)   // zero pad slot c=7
            ((float2*)(sm + OFF_XD))[tid * 8 + 7] = make_float2(0.f, 0.f);
    }
    __syncthreads();

    // ---------------- Phase 1 (+1b): h = x @ Wh ; f1/f2 = x @ (Wh@a) ----------------
    {
        const int hh = wid >> 1;           // head
        const int jh = wid & 1;            // j-half
        const float* wg = W_heads + hh * (NHn * HDn) + lane;
        ull w[NHn];
        #pragma unroll
        for (int n = 0; n < NHn; n++)
            w[n] = pack2(__ldg(wg + n * HDn), __ldg(wg + n * HDn + 32));
        const float2 a1f = make_float2(__ldg(a_heads + hh * 128 + lane),
                                       __ldg(a_heads + hh * 128 + lane + 32));
        const float2 a2f = make_float2(__ldg(a_heads + hh * 128 + 64 + lane),
                                       __ldg(a_heads + hh * 128 + 64 + lane + 32));
        float wa1[NHn], wa2[NHn];
        #pragma unroll
        for (int n = 0; n < NHn; n++) {
            float2 wf = unpk(w[n]);
            float p1 = wf.x * a1f.x + wf.y * a1f.y;
            float p2 = wf.x * a2f.x + wf.y * a2f.y;
            warp_sum2(p1, p2);
            wa1[n] = p1; wa2[n] = p2;
        }

        const int j0 = jh * 11, cnt = 11 - jh;
        const ulonglong2* xd2 = (const ulonglong2*)(sm + OFF_XD);
        ull* hout = (ull*)(sm + OFF_H);
        for (int jj = 0; jj < cnt; jj++) {
            const int j = j0 + jj;
            ulonglong2 x01 = xd2[j * 4 + 0];
            ulonglong2 x23 = xd2[j * 4 + 1];
            ulonglong2 x45 = xd2[j * 4 + 2];
            ulonglong2 x67 = xd2[j * 4 + 3];   // .y is pad
            ull acc = 0ull;
            ffma2(acc, x01.x, w[0]); ffma2(acc, x01.y, w[1]);
            ffma2(acc, x23.x, w[2]); ffma2(acc, x23.y, w[3]);
            ffma2(acc, x45.x, w[4]); ffma2(acc, x45.y, w[5]);
            ffma2(acc, x67.x, w[6]);
            hout[(hh * Jn + j) * 32 + lane] = acc;
            if (lane == 0) {
                float xs0 = unpk(x01.x).x, xs1 = unpk(x01.y).x;
                float xs2 = unpk(x23.x).x, xs3 = unpk(x23.y).x;
                float xs4 = unpk(x45.x).x, xs5 = unpk(x45.y).x;
                float xs6 = unpk(x67.x).x;
                float f1 = xs0 * wa1[0] + xs1 * wa1[1] + xs2 * wa1[2] + xs3 * wa1[3]
                         + xs4 * wa1[4] + xs5 * wa1[5] + xs6 * wa1[6];
                float f2 = xs0 * wa2[0] + xs1 * wa2[1] + xs2 * wa2[2] + xs3 * wa2[3]
                         + xs4 * wa2[4] + xs5 * wa2[5] + xs6 * wa2[6];
                sm[OFF_F1 + hh * Jn + j] = f1;
                sm[OFF_F2 + hh * Jn + j] = f2;
            }
        }
    }
    __syncthreads();

    // ---------------- Phase 2a: per-row softmax, float4 row writes ----------------
    if (tid < Hn * Jn) {
        const int hh = tid / Jn;
        const float fi = sm[OFF_F1 + tid];
        const float* f2r = sm + OFF_F2 + hh * Jn;
        float ebuf[Jn];
        float m = -1e30f;
        #pragma unroll
        for (int j = 0; j < Jn; j++) {
            float e = fi + f2r[j];
            e = e > 0.f ? e : 0.2f * e;
            ebuf[j] = e;
            m = fmaxf(m, e);
        }
        float s = 0.f;
        #pragma unroll
        for (int j = 0; j < Jn; j++) { float t = __expf(ebuf[j] - m); ebuf[j] = t; s += t; }
        float inv = 1.f / s;
        float* arow = sm + OFF_ATTN + tid * ATT_LD;
        #pragma unroll
        for (int q = 0; q < 5; q++)
            ((float4*)arow)[q] = make_float4(ebuf[4 * q] * inv, ebuf[4 * q + 1] * inv,
                                             ebuf[4 * q + 2] * inv, ebuf[4 * q + 3] * inv);
        arow[20] = ebuf[20] * inv;
    }
    __syncthreads();

    // ---------------- Phase 2b: hp = elu(attn @ h) -> hpT[k][i], i-quad float4 stores ----------------
    {
        const int hh = wid >> 1;
        const int ihalf = wid & 1;
        ull hvec[Jn];
        const ull* hbase = (const ull*)(sm + OFF_H) + hh * Jn * 32 + lane;
        #pragma unroll
        for (int j = 0; j < Jn; j++) hvec[j] = hbase[j * 32];

        const float* atbase = sm + OFF_ATTN + hh * Jn * ATT_LD;
        float* row_a = sm + OFF_HPT + (hh * HDn + lane) * HPT_LD;
        float* row_b = row_a + 32 * HPT_LD;
        const int q0 = ihalf ? 3 : 0;
        const int qn = ihalf ? 2 : 3;
        for (int qq = 0; qq < qn; qq++) {
            const int i = (q0 + qq) * 4;
            ull a0 = att_dot(atbase + i * ATT_LD, hvec);
            ull a1 = att_dot(atbase + (i + 1) * ATT_LD, hvec);
            ull a2 = att_dot(atbase + (i + 2) * ATT_LD, hvec);
            ull a3 = att_dot(atbase + (i + 3) * ATT_LD, hvec);
            float2 e0 = unpk(a0), e1 = unpk(a1), e2 = unpk(a2), e3 = unpk(a3);
            *(float4*)(row_a + i) = make_float4(elu1(e0.x), elu1(e1.x), elu1(e2.x), elu1(e3.x));
            *(float4*)(row_b + i) = make_float4(elu1(e0.y), elu1(e1.y), elu1(e2.y), elu1(e3.y));
        }
        if (ihalf) {   // i = 20
            ull a0 = att_dot(atbase + 20 * ATT_LD, hvec);
            float2 e0 = unpk(a0);
            row_a[20] = elu1(e0.x);
            row_b[20] = elu1(e0.y);
        }
    }
    __syncthreads();

    // ---------------- Phase 3: h2 = hp @ W_out, 8 k-slices x all 21 j ----------------
    {
        const int kh = wid;                // 32 k per warp
        const float* wp = W_out + (kh * 32) * HDn + lane;
        const float* hrow = sm + OFF_HPT + (kh * 32) * HPT_LD;
        ull acc[10][2];
        #pragma unroll
        for (int q = 0; q < 10; q++) { acc[q][0] = 0ull; acc[q][1] = 0ull; }
        float a20a = 0.f, a20b = 0.f;
        #pragma unroll 4
        for (int k = 0; k < 32; k++) {
            float wa = __ldg(wp), wb = __ldg(wp + 32);
            wp += HDn;
            ull uwa = dup2(wa), uwb = dup2(wb);
            ulonglong2 p0 = *(const ulonglong2*)(hrow);        // j0..3
            ulonglong2 p1 = *(const ulonglong2*)(hrow + 4);    // j4..7
            ulonglong2 p2 = *(const ulonglong2*)(hrow + 8);    // j8..11
            ulonglong2 p3 = *(const ulonglong2*)(hrow + 12);   // j12..15
            ulonglong2 p4 = *(const ulonglong2*)(hrow + 16);   // j16..19
            float h20 = hrow[20];
            hrow += HPT_LD;
            ffma2(acc[0][0], p0.x, uwa); ffma2(acc[0][1], p0.x, uwb);
            ffma2(acc[1][0], p0.y, uwa); ffma2(acc[1][1], p0.y, uwb);
            ffma2(acc[2][0], p1.x, uwa); ffma2(acc[2][1], p1.x, uwb);
            ffma2(acc[3][0], p1.y, uwa); ffma2(acc[3][1], p1.y, uwb);
            ffma2(acc[4][0], p2.x, uwa); ffma2(acc[4][1], p2.x, uwb);
            ffma2(acc[5][0], p2.y, uwa); ffma2(acc[5][1], p2.y, uwb);
            ffma2(acc[6][0], p3.x, uwa); ffma2(acc[6][1], p3.x, uwb);
            ffma2(acc[7][0], p3.y, uwa); ffma2(acc[7][1], p3.y, uwb);
            ffma2(acc[8][0], p4.x, uwa); ffma2(acc[8][1], p4.x, uwb);
            ffma2(acc[9][0], p4.y, uwa); ffma2(acc[9][1], p4.y, uwb);
            a20a = fmaf(h20, wa, a20a);
            a20b = fmaf(h20, wb, a20b);
        }

        // Stage A: warps 0-3 store their slices to RED (aliases dead h)
        if (wid < 4) {
            float* RED = sm + OFF_H + wid * (Jn * HDn);
            #pragma unroll
            for (int q = 0; q < 10; q++) {
                float2 va = unpk(acc[q][0]);
                float2 vb = unpk(acc[q][1]);
                RED[(2 * q) * 64 + lane]          = va.x;
                RED[(2 * q + 1) * 64 + lane]      = va.y;
                RED[(2 * q) * 64 + lane + 32]     = vb.x;
                RED[(2 * q + 1) * 64 + lane + 32] = vb.y;
            }
            RED[20 * 64 + lane]      = a20a;
            RED[20 * 64 + lane + 32] = a20b;
        }
        __syncthreads();
        // Stage B: warps 4-7 add in place
        if (wid >= 4) {
            float* RED = sm + OFF_H + (wid - 4) * (Jn * HDn);
            #pragma unroll
            for (int q = 0; q < 10; q++) {
                float2 va = unpk(acc[q][0]);
                float2 vb = unpk(acc[q][1]);
                RED[(2 * q) * 64 + lane]          += va.x;
                RED[(2 * q + 1) * 64 + lane]      += va.y;
                RED[(2 * q) * 64 + lane + 32]     += vb.x;
                RED[(2 * q + 1) * 64 + lane + 32] += vb.y;
            }
            RED[20 * 64 + lane]      += a20a;
            RED[20 * 64 + lane + 32] += a20b;
        }
    }
    __syncthreads();

    // ---------------- Phase 3r (+4a): reduce 4 slices -> h2; f1b/f2b via shuffles ----------------
    {
        const ull* RED = (const ull*)(sm + OFF_H);   // [4][672] ull (consecutive-d pairs)
        const float2 ao1 = make_float2(__ldg(a_out + 2 * lane), __ldg(a_out + 2 * lane + 1));
        const float2 ao2 = make_float2(__ldg(a_out + 64 + 2 * lane), __ldg(a_out + 64 + 2 * lane + 1));
        ull* h2 = (ull*)(sm + OFF_H2);
        #pragma unroll
        for (int it = 0; it < 3; it++) {
            const int s = tid + it * 256;           // slot = j*32 + t
            if (s < Jn * 32) {                      // warp-uniform (672 % 32 == 0)
                ull v = RED[s];
                fadd2(v, v, RED[s + 672]);
                ull v2; fadd2(v2, RED[s + 1344], RED[s + 2016]);
                fadd2(v, v, v2);
                h2[s] = v;
                float2 vf = unpk(v);
                float p1 = vf.x * ao1.x + vf.y * ao1.y;
                float p2 = vf.x * ao2.x + vf.y * ao2.y;
                warp_sum2(p1, p2);
                if (lane == 0) {
                    sm[OFF_F1B + (s >> 5)] = p1;
                    sm[OFF_F2B + (s >> 5)] = p2;
                }
            }
        }
    }
    __syncthreads();

    // ---------------- Phase 4b: second softmax -> AT2 (aliases ATTN), float4 writes ----------------
    if (tid < Jn) {
        const float fi = sm[OFF_F1B + tid];
        float ebuf[Jn];
        float m = -1e30f;
        #pragma unroll
        for (int j = 0; j < Jn; j++) {
            float e = fi + sm[OFF_F2B + j];
            e = e > 0.f ? e : 0.2f * e;
            ebuf[j] = e;
            m = fmaxf(m, e);
        }
        float s = 0.f;
        #pragma unroll
        for (int j = 0; j < Jn; j++) { float t = __expf(ebuf[j] - m); ebuf[j] = t; s += t; }
        float inv = 1.f / s;
        float* arow = sm + OFF_AT2 + tid * ATT_LD;
        #pragma unroll
        for (int q = 0; q < 5; q++)
            ((float4*)arow)[q] = make_float4(ebuf[4 * q] * inv, ebuf[4 * q + 1] * inv,
                                             ebuf[4 * q + 2] * inv, ebuf[4 * q + 3] * inv);
        arow[20] = ebuf[20] * inv;
    }
    __syncthreads();

    // ---------------- Phase 4c+4d fused: row = elu(attn2 @ h2); log_softmax; write out ----------------
    {
        ull h2v[Jn];
        const ull* h2b = (const ull*)(sm + OFF_H2) + lane;
        #pragma unroll
        for (int j = 0; j < Jn; j++) h2v[j] = h2b[j * 32];
        for (int i = wid; i < Jn; i += 8) {
            ull acc = att_dot(sm + OFF_AT2 + i * ATT_LD, h2v);
            float2 e = unpk(acc);
            float vx = elu1(e.x), vy = elu1(e.y);
            float m = warp_max(fmaxf(vx, vy));
            float s = warp_sum(__expf(vx - m) + __expf(vy - m));
            float lse = m + __logf(s);
            ull* op = (ull*)(out + (long long)pair * (Jn * HDn) + i * HDn);
            op[lane] = pack2(vx - lse, vy - lse);
        }
    }
}

extern "C" void kernel_launch(void* const* d_in, const int* in_sizes, int n_in,
                              void* d_out, int out_size)
{
    const float* inp = (const float*)d_in[0];
    // d_in[1] = seq_start_end (unused by the reference computation)
    const float* Wh  = (const float*)d_in[2];
    const float* ah  = (const float*)d_in[3];
    const float* Wo  = (const float*)d_in[4];
    const float* ao  = (const float*)d_in[5];
    float* out = (float*)d_out;

    const int npairs = in_sizes[0] / (Jn * NHn);   // 16*1024 = 16384

    cudaFuncSetAttribute(gat_kernel, cudaFuncAttributeMaxDynamicSharedMemorySize, SMEM_BYTES);
    gat_kernel<<<npairs, NTHREADS, SMEM_BYTES>>>(inp, Wh, ah, Wo, ao, out);
}

// round 12
// speedup vs baseline: 3.2344x; 1.0352x over previous
#include <cuda_runtime.h>
#include <math.h>

#define Jn 21
#define NHn 7
#define Hn 4
#define HDn 64
#define NTHREADS 256
#define HPT_LD 28
#define ATT_LD 28

typedef unsigned long long ull;

// ---- shared memory layout (float offsets) ----
constexpr int OFF_H    = 0;                              // 4*21*64 = 5376 (alias: RED partials in ph3)
constexpr int OFF_HPT  = OFF_H + Hn * Jn * HDn;          // 256*28  = 7168
constexpr int OFF_ATTN = OFF_HPT + 256 * HPT_LD;         // 4*21*28 = 2352 (alias: AT2 in ph4b)
constexpr int OFF_XD   = OFF_ATTN + Hn * Jn * ATT_LD;    // 21*8*2  = 336 (dup f2)
constexpr int OFF_F1   = OFF_XD + Jn * 8 * 2;            // 84
constexpr int OFF_F2   = OFF_F1 + Hn * Jn;               // 84
constexpr int OFF_H2   = OFF_F2 + Hn * Jn;               // 21*64 = 1344
constexpr int OFF_F1B  = OFF_H2 + Jn * HDn;              // 21
constexpr int OFF_F2B  = OFF_F1B + Jn;                   // 21
constexpr int OFF_AT2  = OFF_ATTN;                       // alias (ATTN dead after ph2b)
constexpr int SMEM_FLOATS = OFF_F2B + Jn;                // 16786
constexpr int SMEM_BYTES  = SMEM_FLOATS * 4;             // ~67.1 KB -> 3 CTAs/SM (201 KB)

static_assert(OFF_HPT % 4 == 0 && OFF_ATTN % 4 == 0 && OFF_XD % 4 == 0, "align16");
static_assert(Hn * Jn * HDn == 4 * Jn * 64, "RED fits H exactly");

__device__ __forceinline__ void ffma2(ull& d, ull a, ull b) {
    asm("fma.rn.f32x2 %0, %1, %2, %3;" : "=l"(d) : "l"(a), "l"(b), "l"(d));
}
__device__ __forceinline__ void fadd2(ull& d, ull a, ull b) {
    asm("add.rn.f32x2 %0, %1, %2;" : "=l"(d) : "l"(a), "l"(b));
}
__device__ __forceinline__ ull dup2(float x) {
    ull r; unsigned xi = __float_as_uint(x);
    asm("mov.b64 %0, {%1, %1};" : "=l"(r) : "r"(xi));
    return r;
}
__device__ __forceinline__ ull pack2(float a, float b) {
    ull r;
    asm("mov.b64 %0, {%1, %2};" : "=l"(r) : "f"(a), "f"(b));
    return r;
}
__device__ __forceinline__ float2 unpk(ull v) {
    float2 r;
    asm("mov.b64 {%0, %1}, %2;" : "=f"(r.x), "=f"(r.y) : "l"(v));
    return r;
}
__device__ __forceinline__ float warp_sum(float v) {
    #pragma unroll
    for (int o = 16; o > 0; o >>= 1) v += __shfl_xor_sync(0xffffffffu, v, o);
    return v;
}
__device__ __forceinline__ float warp_max(float v) {
    #pragma unroll
    for (int o = 16; o > 0; o >>= 1) v = fmaxf(v, __shfl_xor_sync(0xffffffffu, v, o));
    return v;
}
__device__ __forceinline__ void warp_sum2(float& a, float& b) {
    #pragma unroll
    for (int o = 16; o > 0; o >>= 1) {
        a += __shfl_xor_sync(0xffffffffu, a, o);
        b += __shfl_xor_sync(0xffffffffu, b, o);
    }
}
__device__ __forceinline__ float elu1(float x) {
    return x > 0.f ? x : (__expf(x) - 1.f);
}

// one attention row (21 coeffs, broadcast) dotted against 21 register-held packed vectors
__device__ __forceinline__ ull att_dot(const float* atp, const ull* hv) {
    const float4* at = (const float4*)atp;
    ull acc = 0ull;
    #pragma unroll
    for (int q = 0; q < 5; q++) {
        float4 a4 = at[q];
        ffma2(acc, dup2(a4.x), hv[q * 4 + 0]);
        ffma2(acc, dup2(a4.y), hv[q * 4 + 1]);
        ffma2(acc, dup2(a4.z), hv[q * 4 + 2]);
        ffma2(acc, dup2(a4.w), hv[q * 4 + 3]);
    }
    ffma2(acc, dup2(atp[20]), hv[20]);
    return acc;
}

__global__ void __launch_bounds__(NTHREADS, 3)
gat_kernel(const float* __restrict__ inp,
           const float* __restrict__ W_heads,
           const float* __restrict__ a_heads,
           const float* __restrict__ W_out,
           const float* __restrict__ a_out,
           float* __restrict__ out)
{
    extern __shared__ float sm[];
    const int tid  = threadIdx.x;
    const int lane = tid & 31;
    const int wid  = tid >> 5;
    const int pair = blockIdx.x;

    // ---------------- Phase 0: stage x (reshaped, duplicated for f32x2) ----------------
    {
        const float* ip = inp + (long long)pair * (Jn * NHn);
        if (tid < Jn * NHn) {
            float v = ip[tid];
            int j, c;
            if (tid < Jn * 3)          { j = tid / 3;          c = tid % 3; }
            else if (tid < 2 * Jn * 3) { int t = tid - Jn * 3; j = t / 3;  c = 3 + t % 3; }
            else                       { j = tid - 2 * Jn * 3; c = 6; }
            ((float2*)(sm + OFF_XD))[j * 8 + c] = make_float2(v, v);
        }
        if (tid < Jn)   // zero pad slot c=7
            ((float2*)(sm + OFF_XD))[tid * 8 + 7] = make_float2(0.f, 0.f);
    }
    __syncthreads();

    // ---------------- Phase 1 (+1b): h = x @ Wh ; f1/f2 = x @ (Wh@a) ----------------
    {
        const int hh = wid >> 1;           // head
        const int jh = wid & 1;            // j-half
        const float* wg = W_heads + hh * (NHn * HDn) + lane;
        ull w[NHn];
        #pragma unroll
        for (int n = 0; n < NHn; n++)
            w[n] = pack2(__ldg(wg + n * HDn), __ldg(wg + n * HDn + 32));
        const float2 a1f = make_float2(__ldg(a_heads + hh * 128 + lane),
                                       __ldg(a_heads + hh * 128 + lane + 32));
        const float2 a2f = make_float2(__ldg(a_heads + hh * 128 + 64 + lane),
                                       __ldg(a_heads + hh * 128 + 64 + lane + 32));
        float wa1[NHn], wa2[NHn];
        #pragma unroll
        for (int n = 0; n < NHn; n++) {
            float2 wf = unpk(w[n]);
            float p1 = wf.x * a1f.x + wf.y * a1f.y;
            float p2 = wf.x * a2f.x + wf.y * a2f.y;
            warp_sum2(p1, p2);
            wa1[n] = p1; wa2[n] = p2;
        }

        const int j0 = jh * 11, cnt = 11 - jh;
        const ulonglong2* xd2 = (const ulonglong2*)(sm + OFF_XD);
        ull* hout = (ull*)(sm + OFF_H);
        for (int jj = 0; jj < cnt; jj++) {
            const int j = j0 + jj;
            ulonglong2 x01 = xd2[j * 4 + 0];
            ulonglong2 x23 = xd2[j * 4 + 1];
            ulonglong2 x45 = xd2[j * 4 + 2];
            ulonglong2 x67 = xd2[j * 4 + 3];   // .y is pad
            ull acc = 0ull;
            ffma2(acc, x01.x, w[0]); ffma2(acc, x01.y, w[1]);
            ffma2(acc, x23.x, w[2]); ffma2(acc, x23.y, w[3]);
            ffma2(acc, x45.x, w[4]); ffma2(acc, x45.y, w[5]);
            ffma2(acc, x67.x, w[6]);
            hout[(hh * Jn + j) * 32 + lane] = acc;
            if (lane == 0) {
                float xs0 = unpk(x01.x).x, xs1 = unpk(x01.y).x;
                float xs2 = unpk(x23.x).x, xs3 = unpk(x23.y).x;
                float xs4 = unpk(x45.x).x, xs5 = unpk(x45.y).x;
                float xs6 = unpk(x67.x).x;
                float f1 = xs0 * wa1[0] + xs1 * wa1[1] + xs2 * wa1[2] + xs3 * wa1[3]
                         + xs4 * wa1[4] + xs5 * wa1[5] + xs6 * wa1[6];
                float f2 = xs0 * wa2[0] + xs1 * wa2[1] + xs2 * wa2[2] + xs3 * wa2[3]
                         + xs4 * wa2[4] + xs5 * wa2[5] + xs6 * wa2[6];
                sm[OFF_F1 + hh * Jn + j] = f1;
                sm[OFF_F2 + hh * Jn + j] = f2;
            }
        }
    }
    __syncthreads();

    // ---------------- Phase 2a: per-row softmax, float4 row writes ----------------
    if (tid < Hn * Jn) {
        const int hh = tid / Jn;
        const float fi = sm[OFF_F1 + tid];
        const float* f2r = sm + OFF_F2 + hh * Jn;
        float ebuf[Jn];
        float m = -1e30f;
        #pragma unroll
        for (int j = 0; j < Jn; j++) {
            float e = fi + f2r[j];
            e = e > 0.f ? e : 0.2f * e;
            ebuf[j] = e;
            m = fmaxf(m, e);
        }
        float s = 0.f;
        #pragma unroll
        for (int j = 0; j < Jn; j++) { float t = __expf(ebuf[j] - m); ebuf[j] = t; s += t; }
        float inv = 1.f / s;
        float* arow = sm + OFF_ATTN + tid * ATT_LD;
        #pragma unroll
        for (int q = 0; q < 5; q++)
            ((float4*)arow)[q] = make_float4(ebuf[4 * q] * inv, ebuf[4 * q + 1] * inv,
                                             ebuf[4 * q + 2] * inv, ebuf[4 * q + 3] * inv);
        arow[20] = ebuf[20] * inv;
    }
    __syncthreads();

    // ---------------- Phase 2b: hp = elu(attn @ h) -> hpT[k][i], i-quad float4 stores ----------------
    {
        const int hh = wid >> 1;
        const int ihalf = wid & 1;
        ull hvec[Jn];
        const ull* hbase = (const ull*)(sm + OFF_H) + hh * Jn * 32 + lane;
        #pragma unroll
        for (int j = 0; j < Jn; j++) hvec[j] = hbase[j * 32];

        const float* atbase = sm + OFF_ATTN + hh * Jn * ATT_LD;
        float* row_a = sm + OFF_HPT + (hh * HDn + lane) * HPT_LD;
        float* row_b = row_a + 32 * HPT_LD;
        const int q0 = ihalf ? 3 : 0;
        const int qn = ihalf ? 2 : 3;
        for (int qq = 0; qq < qn; qq++) {
            const int i = (q0 + qq) * 4;
            ull a0 = att_dot(atbase + i * ATT_LD, hvec);
            ull a1 = att_dot(atbase + (i + 1) * ATT_LD, hvec);
            ull a2 = att_dot(atbase + (i + 2) * ATT_LD, hvec);
            ull a3 = att_dot(atbase + (i + 3) * ATT_LD, hvec);
            float2 e0 = unpk(a0), e1 = unpk(a1), e2 = unpk(a2), e3 = unpk(a3);
            *(float4*)(row_a + i) = make_float4(elu1(e0.x), elu1(e1.x), elu1(e2.x), elu1(e3.x));
            *(float4*)(row_b + i) = make_float4(elu1(e0.y), elu1(e1.y), elu1(e2.y), elu1(e3.y));
        }
        if (ihalf) {   // i = 20
            ull a0 = att_dot(atbase + 20 * ATT_LD, hvec);
            float2 e0 = unpk(a0);
            row_a[20] = elu1(e0.x);
            row_b[20] = elu1(e0.y);
        }
    }
    __syncthreads();

    // ---------------- Phase 3: h2 = hp @ W_out, 8 k-slices x all 21 j (W via L2, __ldcg) ----------------
    {
        const int kh = wid;                // 32 k per warp
        const float* wp = W_out + (kh * 32) * HDn + lane;
        const float* hrow = sm + OFF_HPT + (kh * 32) * HPT_LD;
        ull acc[10][2];
        #pragma unroll
        for (int q = 0; q < 10; q++) { acc[q][0] = 0ull; acc[q][1] = 0ull; }
        float a20a = 0.f, a20b = 0.f;
        #pragma unroll 2
        for (int k = 0; k < 32; k++) {
            float wa = __ldcg(wp), wb = __ldcg(wp + 32);
            wp += HDn;
            ull uwa = dup2(wa), uwb = dup2(wb);
            ulonglong2 p0 = *(const ulonglong2*)(hrow);        // j0..3
            ulonglong2 p1 = *(const ulonglong2*)(hrow + 4);    // j4..7
            ulonglong2 p2 = *(const ulonglong2*)(hrow + 8);    // j8..11
            ulonglong2 p3 = *(const ulonglong2*)(hrow + 12);   // j12..15
            ulonglong2 p4 = *(const ulonglong2*)(hrow + 16);   // j16..19
            float h20 = hrow[20];
            hrow += HPT_LD;
            ffma2(acc[0][0], p0.x, uwa); ffma2(acc[0][1], p0.x, uwb);
            ffma2(acc[1][0], p0.y, uwa); ffma2(acc[1][1], p0.y, uwb);
            ffma2(acc[2][0], p1.x, uwa); ffma2(acc[2][1], p1.x, uwb);
            ffma2(acc[3][0], p1.y, uwa); ffma2(acc[3][1], p1.y, uwb);
            ffma2(acc[4][0], p2.x, uwa); ffma2(acc[4][1], p2.x, uwb);
            ffma2(acc[5][0], p2.y, uwa); ffma2(acc[5][1], p2.y, uwb);
            ffma2(acc[6][0], p3.x, uwa); ffma2(acc[6][1], p3.x, uwb);
            ffma2(acc[7][0], p3.y, uwa); ffma2(acc[7][1], p3.y, uwb);
            ffma2(acc[8][0], p4.x, uwa); ffma2(acc[8][1], p4.x, uwb);
            ffma2(acc[9][0], p4.y, uwa); ffma2(acc[9][1], p4.y, uwb);
            a20a = fmaf(h20, wa, a20a);
            a20b = fmaf(h20, wb, a20b);
        }

        // Stage A: warps 0-3 store their slices to RED (aliases dead h)
        if (wid < 4) {
            float* RED = sm + OFF_H + wid * (Jn * HDn);
            #pragma unroll
            for (int q = 0; q < 10; q++) {
                float2 va = unpk(acc[q][0]);
                float2 vb = unpk(acc[q][1]);
                RED[(2 * q) * 64 + lane]          = va.x;
                RED[(2 * q + 1) * 64 + lane]      = va.y;
                RED[(2 * q) * 64 + lane + 32]     = vb.x;
                RED[(2 * q + 1) * 64 + lane + 32] = vb.y;
            }
            RED[20 * 64 + lane]      = a20a;
            RED[20 * 64 + lane + 32] = a20b;
        }
        __syncthreads();
        // Stage B: warps 4-7 add in place
        if (wid >= 4) {
            float* RED = sm + OFF_H + (wid - 4) * (Jn * HDn);
            #pragma unroll
            for (int q = 0; q < 10; q++) {
                float2 va = unpk(acc[q][0]);
                float2 vb = unpk(acc[q][1]);
                RED[(2 * q) * 64 + lane]          += va.x;
                RED[(2 * q + 1) * 64 + lane]      += va.y;
                RED[(2 * q) * 64 + lane + 32]     += vb.x;
                RED[(2 * q + 1) * 64 + lane + 32] += vb.y;
            }
            RED[20 * 64 + lane]      += a20a;
            RED[20 * 64 + lane + 32] += a20b;
        }
    }
    __syncthreads();

    // ---------------- Phase 3r (+4a): reduce 4 slices -> h2; f1b/f2b via shuffles ----------------
    {
        const ull* RED = (const ull*)(sm + OFF_H);   // [4][672] ull (consecutive-d pairs)
        const float2 ao1 = make_float2(__ldg(a_out + 2 * lane), __ldg(a_out + 2 * lane + 1));
        const float2 ao2 = make_float2(__ldg(a_out + 64 + 2 * lane), __ldg(a_out + 64 + 2 * lane + 1));
        ull* h2 = (ull*)(sm + OFF_H2);
        #pragma unroll
        for (int it = 0; it < 3; it++) {
            const int s = tid + it * 256;           // slot = j*32 + t
            if (s < Jn * 32) {                      // warp-uniform (672 % 32 == 0)
                ull v = RED[s];
                fadd2(v, v, RED[s + 672]);
                ull v2; fadd2(v2, RED[s + 1344], RED[s + 2016]);
                fadd2(v, v, v2);
                h2[s] = v;
                float2 vf = unpk(v);
                float p1 = vf.x * ao1.x + vf.y * ao1.y;
                float p2 = vf.x * ao2.x + vf.y * ao2.y;
                warp_sum2(p1, p2);
                if (lane == 0) {
                    sm[OFF_F1B + (s >> 5)] = p1;
                    sm[OFF_F2B + (s >> 5)] = p2;
                }
            }
        }
    }
    __syncthreads();

    // ---------------- Phase 4b: second softmax -> AT2 (aliases ATTN), float4 writes ----------------
    if (tid < Jn) {
        const float fi = sm[OFF_F1B + tid];
        float ebuf[Jn];
        float m = -1e30f;
        #pragma unroll
        for (int j = 0; j < Jn; j++) {
            float e = fi + sm[OFF_F2B + j];
            e = e > 0.f ? e : 0.2f * e;
            ebuf[j] = e;
            m = fmaxf(m, e);
        }
        float s = 0.f;
        #pragma unroll
        for (int j = 0; j < Jn; j++) { float t = __expf(ebuf[j] - m); ebuf[j] = t; s += t; }
        float inv = 1.f / s;
        float* arow = sm + OFF_AT2 + tid * ATT_LD;
        #pragma unroll
        for (int q = 0; q < 5; q++)
            ((float4*)arow)[q] = make_float4(ebuf[4 * q] * inv, ebuf[4 * q + 1] * inv,
                                             ebuf[4 * q + 2] * inv, ebuf[4 * q + 3] * inv);
        arow[20] = ebuf[20] * inv;
    }
    __syncthreads();

    // ---------------- Phase 4c+4d fused: row = elu(attn2 @ h2); log_softmax; write out ----------------
    {
        ull h2v[Jn];
        const ull* h2b = (const ull*)(sm + OFF_H2) + lane;
        #pragma unroll
        for (int j = 0; j < Jn; j++) h2v[j] = h2b[j * 32];
        for (int i = wid; i < Jn; i += 8) {
            ull acc = att_dot(sm + OFF_AT2 + i * ATT_LD, h2v);
            float2 e = unpk(acc);
            float vx = elu1(e.x), vy = elu1(e.y);
            float m = warp_max(fmaxf(vx, vy));
            float s = warp_sum(__expf(vx - m) + __expf(vy - m));
            float lse = m + __logf(s);
            ull* op = (ull*)(out + (long long)pair * (Jn * HDn) + i * HDn);
            op[lane] = pack2(vx - lse, vy - lse);
        }
    }
}

extern "C" void kernel_launch(void* const* d_in, const int* in_sizes, int n_in,
                              void* d_out, int out_size)
{
    const float* inp = (const float*)d_in[0];
    // d_in[1] = seq_start_end (unused by the reference computation)
    const float* Wh  = (const float*)d_in[2];
    const float* ah  = (const float*)d_in[3];
    const float* Wo  = (const float*)d_in[4];
    const float* ao  = (const float*)d_in[5];
    float* out = (float*)d_out;

    const int npairs = in_sizes[0] / (Jn * NHn);   // 16*1024 = 16384

    cudaFuncSetAttribute(gat_kernel, cudaFuncAttributeMaxDynamicSharedMemorySize, SMEM_BYTES);
    gat_kernel<<<npairs, NTHREADS, SMEM_BYTES>>>(inp, Wh, ah, Wo, ao, out);
}